// round 11
// baseline (speedup 1.0000x reference)
#include <cuda_runtime.h>
#include <cuda_bf16.h>
#include <math.h>
#include <stdint.h>

// ---------------- problem constants ----------------
#define BB   64
#define LL   1024
#define HH   256
#define H2   512
#define CC   111
#define TT   64
#define CIN  1024
#define DD   256
#define KCAT 879
#define NGI  1024
#define KX   623
#define XW   512        // xcat: [ctx(256) | h(256)]
#define GM   512
#define GN   1024
#define GK   1024

// ---------------- device scratch ----------------
__device__ __nv_bfloat16 g_Fh[(long)BB * H2 * LL];  // rows 0-255: ctx feats, 256-511: Wf
__device__ float g_scores[4 * BB * LL];
__device__ float g_cov[BB * LL];
__device__ float g_h[2 * BB * HH];
__device__ float g_context[BB * HH];
__device__ float g_gi[BB * NGI];
__device__ float g_xcat[BB * XW];
__device__ float g_WcatT[KCAT * NGI];   // rows: emb 0-255, ctx 256-511, cnt 512-622, h 623-878
__device__ float g_gbias[NGI];
__device__ float g_gemb[CC * NGI];
__device__ float g_gcntb[BB * NGI];
__device__ float g_W2[H2 * CIN];
__device__ float g_peB[H2 * LL];
__device__ float g_E[H2 * LL];

__device__ __forceinline__ float ftanh(float x) {
    float y; asm("tanh.approx.f32 %0, %1;" : "=f"(y) : "f"(x)); return y;
}
__device__ __forceinline__ float pe_val(int l, int o) {
    float f = expf((float)(o & ~1) * (-9.210340371976184f / 512.f));
    float a = (float)l * f;
    return (o & 1) ? cosf(a) : sinf(a);
}
__device__ __forceinline__ uint32_t s2u(const void* p) {
    return (uint32_t)__cvta_generic_to_shared(p);
}
__device__ __forceinline__ void ldsm4(uint32_t* r, uint32_t a) {
    asm volatile("ldmatrix.sync.aligned.m8n8.x4.shared.b16 {%0,%1,%2,%3}, [%4];"
                 : "=r"(r[0]), "=r"(r[1]), "=r"(r[2]), "=r"(r[3]) : "r"(a));
}
__device__ __forceinline__ void ldsm4t(uint32_t* r, uint32_t a) {
    asm volatile("ldmatrix.sync.aligned.m8n8.x4.trans.shared.b16 {%0,%1,%2,%3}, [%4];"
                 : "=r"(r[0]), "=r"(r[1]), "=r"(r[2]), "=r"(r[3]) : "r"(a));
}
__device__ __forceinline__ void mma_bf16(float* d, const uint32_t* a, const uint32_t* b) {
    asm volatile(
        "mma.sync.aligned.m16n8k16.row.col.f32.bf16.bf16.f32 "
        "{%0,%1,%2,%3}, {%4,%5,%6,%7}, {%8,%9}, {%0,%1,%2,%3};\n"
        : "+f"(d[0]), "+f"(d[1]), "+f"(d[2]), "+f"(d[3])
        : "r"(a[0]), "r"(a[1]), "r"(a[2]), "r"(a[3]), "r"(b[0]), "r"(b[1]));
}
__device__ __forceinline__ uint32_t f2bf2(float x, float y) {
    __nv_bfloat162 h = __floats2bfloat162_rn(x, y);
    return *reinterpret_cast<uint32_t*>(&h);
}

// ---------------- prep ----------------
__global__ void prep_kernel(const float* __restrict__ wih, const float* __restrict__ whh,
                            const float* __restrict__ bih, const float* __restrict__ bhh,
                            const float* __restrict__ convw, const float* __restrict__ convb) {
    const long R1 = (long)KCAT * NGI;
    const long R2 = R1 + NGI;
    const long R3 = R2 + 256L * CIN;
    const long R4 = R3 + (long)H2 * LL;
    const long R5 = R4 + 256L * LL;
    const long ZTOT = 2L*BB*HH + BB*LL + BB*HH + BB*XW;
    const long TOTAL = R5 + ZTOT;
    for (long idx = (long)blockIdx.x * blockDim.x + threadIdx.x; idx < TOTAL;
         idx += (long)gridDim.x * blockDim.x) {
        long i = idx;
        if (i < R1) {
            int k = (int)(i >> 10), j = (int)(i & 1023);
            float v = 0.f;
            if (j < 768) {
                if (k < KX) v = wih[j * KX + k];
                else if (k < KCAT && j < 512) v = whh[j * HH + (k - KX)];
            } else {
                if (k >= KX && k < KCAT) v = whh[(j - 768 + 512) * HH + (k - KX)];
            }
            g_WcatT[i] = v; continue;
        }
        if (i < R2) { int j = (int)(i - R1);
            g_gbias[j] = (j < 512) ? bih[j] + bhh[j] : (j < 768) ? bih[j] : bhh[j - 256];
            continue; }
        if (i < R3) { long p = i - R2; g_W2[p] = convw[p]; continue; }
        if (i < R4) { long p = i - R3; int o = (int)(p >> 10), l = (int)(p & 1023);
            g_peB[p] = pe_val(l, o) + convb[o]; continue; }
        if (i < R5) { long p = i - R4; int m = (int)(p >> 10), l = (int)(p & 1023);
            g_E[p] = convb[m] + pe_val(l, m); continue; }
        long p = i - R5;
        if (p < 2L*BB*HH) { g_h[p] = 0.f; continue; } p -= 2L*BB*HH;
        if (p < BB*LL) { g_cov[p] = 0.f; continue; } p -= BB*LL;
        if (p < BB*HH) { g_context[p] = 0.f; continue; } p -= BB*HH;
        g_xcat[p] = 0.f;
    }
}

// ---------------- gemb[c] = emb[c] @ Wemb  (grid 111 x 4, scalar MLP) ----------------
__global__ __launch_bounds__(256) void gemb_kernel(const float* __restrict__ emb) {
    const int c = blockIdx.x, j = blockIdx.y * 256 + threadIdx.x;
    __shared__ float s_e[DD];
    s_e[threadIdx.x] = emb[c * DD + threadIdx.x];
    __syncthreads();
    float a0 = 0.f, a1 = 0.f;
#pragma unroll 16
    for (int k = 0; k < DD; k += 2) {
        a0 = fmaf(s_e[k],     g_WcatT[(long)k * NGI + j], a0);
        a1 = fmaf(s_e[k + 1], g_WcatT[(long)(k + 1) * NGI + j], a1);
    }
    g_gemb[(long)c * NGI + j] = a0 + a1;
}

// ---------------- gcntb[b] = gbias + count[b] @ Wcnt (grid 64 x 4) ----------------
__global__ __launch_bounds__(256) void gcnt_kernel(const float* __restrict__ count) {
    const int b = blockIdx.x, j = blockIdx.y * 256 + threadIdx.x;
    __shared__ float s_c[CC];
    if (threadIdx.x < CC) s_c[threadIdx.x] = count[b * CC + threadIdx.x];
    __syncthreads();
    float acc = g_gbias[j];
#pragma unroll 8
    for (int k = 0; k < CC; k++)
        acc = fmaf(s_c[k], g_WcatT[(long)(512 + k) * NGI + j], acc);
    g_gcntb[(long)b * NGI + j] = acc;
}

// ---------------- SIMT SGEMM (small prep GEMMs only) ----------------
__global__ __launch_bounds__(256, 2) void sgemm_kernel(
    const float* __restrict__ A, const float* __restrict__ Bg, float* __restrict__ Cg,
    int M, int N, int K, const float* __restrict__ bias) {
    const int bx = blockIdx.x, by = blockIdx.y, b = blockIdx.z;
    const float* Bp = Bg + (long)b * K * N;
    float* Cp = Cg + (long)b * M * N;
    const int tid = threadIdx.x;
    __shared__ float As[8][128];
    __shared__ float Bs[8][128];
    float acc[8][8];
#pragma unroll
    for (int i = 0; i < 8; i++)
#pragma unroll
        for (int j = 0; j < 8; j++) acc[i][j] = 0.f;
    const int m0 = by * 128, n0 = bx * 128;
    const int arow = tid >> 1, acol = (tid & 1) * 4;
    const int brow = tid >> 5, bcol = (tid & 31) * 4;
    const int ty = tid >> 4, tx = tid & 15;
    for (int k0 = 0; k0 < K; k0 += 8) {
        float4 a4 = *(const float4*)&A[(long)(m0 + arow) * K + k0 + acol];
        As[acol + 0][arow] = a4.x; As[acol + 1][arow] = a4.y;
        As[acol + 2][arow] = a4.z; As[acol + 3][arow] = a4.w;
        *(float4*)&Bs[brow][bcol] = *(const float4*)&Bp[(long)(k0 + brow) * N + n0 + bcol];
        __syncthreads();
#pragma unroll
        for (int kk = 0; kk < 8; kk++) {
            float ra[8], rb[8];
#pragma unroll
            for (int i = 0; i < 8; i++) ra[i] = As[kk][ty * 8 + i];
#pragma unroll
            for (int j = 0; j < 8; j++) rb[j] = Bs[kk][tx * 8 + j];
#pragma unroll
            for (int i = 0; i < 8; i++)
#pragma unroll
                for (int j = 0; j < 8; j++) acc[i][j] = fmaf(ra[i], rb[j], acc[i][j]);
        }
        __syncthreads();
    }
#pragma unroll
    for (int i = 0; i < 8; i++) {
        int m = m0 + ty * 8 + i;
        float bia = bias ? bias[m] : 0.f;
#pragma unroll
        for (int j = 0; j < 8; j++)
            Cp[(long)m * N + n0 + tx * 8 + j] = acc[i][j] + bia;
    }
}

// ---------------- bf16 tensor-core main GEMM, fp32 in (reg convert), bf16 out ------
__global__ __launch_bounds__(256, 2) void mma_gemm_kernel(
    const float* __restrict__ A, const float* __restrict__ Bg,
    __nv_bfloat16* __restrict__ Cg, const float* __restrict__ Etab) {
    const int tid = threadIdx.x;
    const int bx = blockIdx.x, by = blockIdx.y, b = blockIdx.z;
    const float* Bp = Bg + (long)b * GK * GN;
    __nv_bfloat16* Cp = Cg + (long)b * GM * GN;
    __shared__ __nv_bfloat16 As[128][40];
    __shared__ __nv_bfloat16 Bs[32][136];
    const int w = tid >> 5, lane = tid & 31;
    const int wm = (w & 3) * 32, wn = (w >> 2) * 64;
    const int m0 = by * 128, n0 = bx * 128;
    const int lg = lane >> 2, lk = lane & 3;

    float acc[2][8][4];
#pragma unroll
    for (int i = 0; i < 2; i++)
#pragma unroll
        for (int j = 0; j < 8; j++)
#pragma unroll
            for (int c = 0; c < 4; c++) acc[i][j][c] = 0.f;

    const int ar = tid >> 1, ac = (tid & 1) * 16;
    const int br = tid >> 3, bc = (tid & 7) * 16;
    const uint32_t aAddr0 = s2u(&As[wm + (lane & 15)][(lane >> 4) * 8]);
    const uint32_t bAddr0 = s2u(&Bs[lane & 15][wn + (lane >> 4) * 8]);

    uint4 ra0, ra1, rb0, rb1;
    {
        const float4* pa = (const float4*)(A + (long)(m0 + ar) * GK + ac);
        const float4* pb = (const float4*)(Bp + (long)br * GN + n0 + bc);
        float4 a0 = pa[0], a1 = pa[1], a2 = pa[2], a3 = pa[3];
        float4 b0 = pb[0], b1 = pb[1], b2 = pb[2], b3 = pb[3];
        ra0 = make_uint4(f2bf2(a0.x,a0.y), f2bf2(a0.z,a0.w), f2bf2(a1.x,a1.y), f2bf2(a1.z,a1.w));
        ra1 = make_uint4(f2bf2(a2.x,a2.y), f2bf2(a2.z,a2.w), f2bf2(a3.x,a3.y), f2bf2(a3.z,a3.w));
        rb0 = make_uint4(f2bf2(b0.x,b0.y), f2bf2(b0.z,b0.w), f2bf2(b1.x,b1.y), f2bf2(b1.z,b1.w));
        rb1 = make_uint4(f2bf2(b2.x,b2.y), f2bf2(b2.z,b2.w), f2bf2(b3.x,b3.y), f2bf2(b3.z,b3.w));
    }

    for (int kt = 0; kt < GK / 32; kt++) {
        *(uint4*)&As[ar][ac]     = ra0;
        *(uint4*)&As[ar][ac + 8] = ra1;
        *(uint4*)&Bs[br][bc]     = rb0;
        *(uint4*)&Bs[br][bc + 8] = rb1;
        __syncthreads();
        if (kt + 1 < GK / 32) {
            int k0 = (kt + 1) * 32;
            const float4* pa = (const float4*)(A + (long)(m0 + ar) * GK + k0 + ac);
            const float4* pb = (const float4*)(Bp + (long)(k0 + br) * GN + n0 + bc);
            float4 a0 = pa[0], a1 = pa[1], a2 = pa[2], a3 = pa[3];
            float4 b0 = pb[0], b1 = pb[1], b2 = pb[2], b3 = pb[3];
            ra0 = make_uint4(f2bf2(a0.x,a0.y), f2bf2(a0.z,a0.w), f2bf2(a1.x,a1.y), f2bf2(a1.z,a1.w));
            ra1 = make_uint4(f2bf2(a2.x,a2.y), f2bf2(a2.z,a2.w), f2bf2(a3.x,a3.y), f2bf2(a3.z,a3.w));
            rb0 = make_uint4(f2bf2(b0.x,b0.y), f2bf2(b0.z,b0.w), f2bf2(b1.x,b1.y), f2bf2(b1.z,b1.w));
            rb1 = make_uint4(f2bf2(b2.x,b2.y), f2bf2(b2.z,b2.w), f2bf2(b3.x,b3.y), f2bf2(b3.z,b3.w));
        }
#pragma unroll
        for (int ks = 0; ks < 2; ks++) {
            uint32_t af[2][4], bf[4][4];
#pragma unroll
            for (int tm = 0; tm < 2; tm++)
                ldsm4(af[tm], aAddr0 + (tm * 16 * 40 + ks * 16) * 2);
#pragma unroll
            for (int p = 0; p < 4; p++)
                ldsm4t(bf[p], bAddr0 + (ks * 16 * 136 + p * 16) * 2);
#pragma unroll
            for (int tn = 0; tn < 8; tn++) {
                mma_bf16(acc[0][tn], af[0], &bf[tn >> 1][(tn & 1) * 2]);
                mma_bf16(acc[1][tn], af[1], &bf[tn >> 1][(tn & 1) * 2]);
            }
        }
        __syncthreads();
    }
#pragma unroll
    for (int tm = 0; tm < 2; tm++) {
#pragma unroll
        for (int tn = 0; tn < 8; tn++) {
            int m = m0 + wm + tm * 16 + lg;
            int n = n0 + wn + tn * 8 + 2 * lk;
            long i0 = (long)m * GN + n;
            long i1 = (long)(m + 8) * GN + n;
            float2 e0 = *(const float2*)&Etab[i0];
            float2 e1 = *(const float2*)&Etab[i1];
            *(__nv_bfloat162*)(Cp + i0) =
                __floats2bfloat162_rn(acc[tm][tn][0] + e0.x, acc[tm][tn][1] + e0.y);
            *(__nv_bfloat162*)(Cp + i1) =
                __floats2bfloat162_rn(acc[tm][tn][2] + e1.x, acc[tm][tn][3] + e1.y);
        }
    }
}

// ---------------- K1: gate finalize + out_{t-1} + attention score partials ----------
__global__ __launch_bounds__(256) void score_kernel(
    int t, int nch,
    const float* __restrict__ count,
    const float* __restrict__ attn_v, const float* __restrict__ attn_vb,
    const float* __restrict__ cov_w, const float* __restrict__ cov_b,
    const float* __restrict__ out_w, const float* __restrict__ out_b,
    float* __restrict__ d_out) {
    const int b = blockIdx.y, cx = blockIdx.x, tid = threadIdx.x;
    float hn = 0.f;
    if (t > 0) {
        const float* gi = g_gi + b * NGI;
        float gr = gi[tid], gz = gi[256 + tid], gin = gi[512 + tid], ghn = gi[768 + tid];
        float hold = g_h[((t - 1) & 1) * BB * HH + b * HH + tid];
        float r = 1.f / (1.f + expf(-gr));
        float z = 1.f / (1.f + expf(-gz));
        float n = tanhf(gin + r * ghn);
        hn = (1.f - z) * n + z * hold;
    }

    if (cx == nch) {  // aux block: h_t, xcat h-part, out_{t-1}
        __shared__ float s_x2[640];
        g_h[(t & 1) * BB * HH + b * HH + tid] = hn;
        if (t < TT) g_xcat[b * XW + 256 + tid] = hn;
        if (t > 0) {
            s_x2[tid] = hn;
            s_x2[256 + tid] = g_context[b * HH + tid];
            if (tid < CC) s_x2[512 + tid] = count[b * CC + tid];
            __syncthreads();
            const int warp = tid >> 5, lane = tid & 31;
            float* op = d_out + ((long)b * TT + (t - 1)) * CC;
#pragma unroll
            for (int i = 0; i < 14; i++) {
                int c = warp * 14 + i;
                if (c < CC) {
                    const float* wrow = out_w + (long)c * KX;
                    float acc = 0.f;
                    for (int k = lane; k < KX; k += 32)
                        acc = fmaf(wrow[k], s_x2[k], acc);
#pragma unroll
                    for (int o = 16; o > 0; o >>= 1)
                        acc += __shfl_xor_sync(0xffffffffu, acc, o);
                    if (lane == 0) op[c] = acc + out_b[c];
                }
            }
        }
        return;
    }

    const int lchunk = cx & 1, hq = cx >> 1, hh0 = hq * 64;
    __shared__ float s_hfull[HH];
    __shared__ float s_base[64], s_cw[64], s_v[64];
    s_hfull[tid] = hn;
    __syncthreads();
    if (tid < 64) {
        int h = hh0 + tid;
        s_base[tid] = cov_b[h] + s_hfull[h];
        s_cw[tid] = cov_w[h];
        s_v[tid] = attn_v[h];
    }
    __syncthreads();

    const int p = lchunk * 256 + tid;
    const float2 cov = *(const float2*)&g_cov[b * LL + 2 * p];
    const __nv_bfloat162* wf2 =
        (const __nv_bfloat162*)(g_Fh + ((long)b * H2 + 256 + hh0) * LL) + p;
    float a0 = (hq == 0) ? attn_vb[0] : 0.f, a1 = 0.f;
    float b0 = 0.f, b1 = 0.f;
#pragma unroll 8
    for (int hh = 0; hh < 64; hh += 2) {
        float2 w0 = __bfloat1622float2(wf2[(long)hh * 512]);
        float2 w1 = __bfloat1622float2(wf2[(long)(hh + 1) * 512]);
        float ba0 = s_base[hh], cw0 = s_cw[hh], vv0 = s_v[hh];
        float ba1 = s_base[hh + 1], cw1 = s_cw[hh + 1], vv1 = s_v[hh + 1];
        a0 = fmaf(vv0, ftanh(fmaf(cov.x, cw0, w0.x + ba0)), a0);
        a1 = fmaf(vv0, ftanh(fmaf(cov.y, cw0, w0.y + ba0)), a1);
        b0 = fmaf(vv1, ftanh(fmaf(cov.x, cw1, w1.x + ba1)), b0);
        b1 = fmaf(vv1, ftanh(fmaf(cov.y, cw1, w1.y + ba1)), b1);
    }
    *(float2*)&g_scores[hq * BB * LL + b * LL + 2 * p] = make_float2(a0 + b0, a1 + b1);
}

// ---------------- K2: softmax + coverage + context + xcat ctx-part + gi init ------
__global__ __launch_bounds__(256) void ctx_kernel(int t, const int* __restrict__ target) {
    const int b = blockIdx.y, c = blockIdx.x, tid = threadIdx.x;
    const int warp = tid >> 5, lane = tid & 31;
    __shared__ float s_alpha[LL];
    __shared__ float s_red[8];

    float4 p0 = ((const float4*)(g_scores + b * LL))[tid];
    float4 p1 = ((const float4*)(g_scores + 1 * BB * LL + b * LL))[tid];
    float4 p2 = ((const float4*)(g_scores + 2 * BB * LL + b * LL))[tid];
    float4 p3 = ((const float4*)(g_scores + 3 * BB * LL + b * LL))[tid];
    float4 sc = make_float4((p0.x + p1.x) + (p2.x + p3.x),
                            (p0.y + p1.y) + (p2.y + p3.y),
                            (p0.z + p1.z) + (p2.z + p3.z),
                            (p0.w + p1.w) + (p2.w + p3.w));
    float mx = fmaxf(fmaxf(sc.x, sc.y), fmaxf(sc.z, sc.w));
#pragma unroll
    for (int o = 16; o > 0; o >>= 1) mx = fmaxf(mx, __shfl_xor_sync(0xffffffffu, mx, o));
    if (lane == 0) s_red[warp] = mx;
    __syncthreads();
    float M = s_red[0];
#pragma unroll
    for (int w = 1; w < 8; w++) M = fmaxf(M, s_red[w]);
    float e0 = __expf(sc.x - M), e1 = __expf(sc.y - M);
    float e2 = __expf(sc.z - M), e3 = __expf(sc.w - M);
    float sm = e0 + e1 + e2 + e3;
#pragma unroll
    for (int o = 16; o > 0; o >>= 1) sm += __shfl_xor_sync(0xffffffffu, sm, o);
    __syncthreads();
    if (lane == 0) s_red[warp] = sm;
    __syncthreads();
    float S = 0.f;
#pragma unroll
    for (int w = 0; w < 8; w++) S += s_red[w];
    float inv = 1.f / S;
    float4 al = make_float4(e0 * inv, e1 * inv, e2 * inv, e3 * inv);
    ((float4*)s_alpha)[tid] = al;
    if (c == 0) {
        float4 cv = ((float4*)(g_cov + b * LL))[tid];
        cv.x += al.x; cv.y += al.y; cv.z += al.z; cv.w += al.w;
        ((float4*)(g_cov + b * LL))[tid] = cv;
    }
    __syncthreads();

    const __nv_bfloat16* fb = g_Fh + (long)b * H2 * LL;
#pragma unroll
    for (int r = 0; r < 4; r++) {
        int d = c * 32 + warp * 4 + r;
        const uint4* row = (const uint4*)(fb + (long)d * LL);
        float sum = 0.f;
#pragma unroll
        for (int it = 0; it < 4; it++) {
            uint4 f8 = row[it * 32 + lane];
            const float4* ap = (const float4*)&s_alpha[(it * 32 + lane) * 8];
            float4 a0 = ap[0], a1 = ap[1];
            float2 f0 = __bfloat1622float2(*(__nv_bfloat162*)&f8.x);
            float2 f1 = __bfloat1622float2(*(__nv_bfloat162*)&f8.y);
            float2 f2 = __bfloat1622float2(*(__nv_bfloat162*)&f8.z);
            float2 f3 = __bfloat1622float2(*(__nv_bfloat162*)&f8.w);
            sum = fmaf(f0.x, a0.x, sum); sum = fmaf(f0.y, a0.y, sum);
            sum = fmaf(f1.x, a0.z, sum); sum = fmaf(f1.y, a0.w, sum);
            sum = fmaf(f2.x, a1.x, sum); sum = fmaf(f2.y, a1.y, sum);
            sum = fmaf(f3.x, a1.z, sum); sum = fmaf(f3.y, a1.w, sum);
        }
#pragma unroll
        for (int o = 16; o > 0; o >>= 1) sum += __shfl_xor_sync(0xffffffffu, sum, o);
        if (lane == 0) {
            g_context[b * HH + d] = sum;
            g_xcat[b * XW + d] = sum;
        }
    }

    if (tid < 128) {
        int y = (t == 0) ? 1 : target[b * TT + (t - 1)];
        int j = c * 128 + tid;
        g_gi[b * NGI + j] = g_gemb[(long)y * NGI + j] + g_gcntb[(long)b * NGI + j];
    }
}

// ---------------- K3: GRU gate GEMM, K=512 ([ctx|h]), K-split atomic ----------------
__global__ __launch_bounds__(256) void gru_gemm_kernel() {
    const int nt = blockIdx.x & 15, ks = blockIdx.x >> 4;
    const int n0 = nt * 64, k0 = ks * 64;
    const int tid = threadIdx.x;
    __shared__ float Xs[16][68];
    __shared__ float Ws[16][64];
    const int ml = tid >> 2, kq = (tid & 3) * 4;
    const int kw = tid >> 4, nn = (tid & 15) * 4;
    const int ty = tid >> 4, tx = tid & 15;
    float acc[4][4];
#pragma unroll
    for (int i = 0; i < 4; i++)
#pragma unroll
        for (int j = 0; j < 4; j++) acc[i][j] = 0.f;

#pragma unroll
    for (int kt = 0; kt < 4; kt++) {
        const int k = k0 + kt * 16;
        float4 x4 = *(const float4*)&g_xcat[ml * XW + k + kq];
        Xs[kq + 0][ml] = x4.x; Xs[kq + 1][ml] = x4.y;
        Xs[kq + 2][ml] = x4.z; Xs[kq + 3][ml] = x4.w;
        const int row = (k < 256) ? (256 + k + kw) : (623 + (k - 256) + kw);
        *(float4*)&Ws[kw][nn] = *(const float4*)&g_WcatT[(long)row * NGI + n0 + nn];
        __syncthreads();
#pragma unroll
        for (int kk = 0; kk < 16; kk++) {
            float rx[4], rw[4];
#pragma unroll
            for (int i = 0; i < 4; i++) rx[i] = Xs[kk][ty * 4 + i];
#pragma unroll
            for (int j = 0; j < 4; j++) rw[j] = Ws[kk][tx * 4 + j];
#pragma unroll
            for (int i = 0; i < 4; i++)
#pragma unroll
                for (int j = 0; j < 4; j++) acc[i][j] = fmaf(rx[i], rw[j], acc[i][j]);
        }
        __syncthreads();
    }
#pragma unroll
    for (int i = 0; i < 4; i++)
#pragma unroll
        for (int j = 0; j < 4; j++)
            atomicAdd(&g_gi[(ty * 4 + i) * NGI + n0 + tx * 4 + j], acc[i][j]);
}

// ---------------- launch ----------------
extern "C" void kernel_launch(void* const* d_in, const int* in_sizes, int n_in,
                              void* d_out, int out_size) {
    const float* fm      = (const float*)d_in[0];
    const float* count   = (const float*)d_in[1];
    const int*   target  = (const int*)d_in[2];
    const float* conv_w  = (const float*)d_in[3];
    const float* conv_b  = (const float*)d_in[4];
    const float* emb     = (const float*)d_in[5];
    const float* gru_wih = (const float*)d_in[6];
    const float* gru_whh = (const float*)d_in[7];
    const float* gru_bih = (const float*)d_in[8];
    const float* gru_bhh = (const float*)d_in[9];
    const float* attn_w  = (const float*)d_in[10];
    const float* attn_b  = (const float*)d_in[11];
    const float* attn_v  = (const float*)d_in[12];
    const float* attn_vb = (const float*)d_in[13];
    const float* cov_w   = (const float*)d_in[14];
    const float* cov_b   = (const float*)d_in[15];
    const float* out_w   = (const float*)d_in[16];
    const float* out_b   = (const float*)d_in[17];
    float* out = (float*)d_out;

    float *pW2, *pPeB, *pE;
    __nv_bfloat16 *pFh;
    cudaGetSymbolAddress((void**)&pFh, g_Fh);
    cudaGetSymbolAddress((void**)&pW2, g_W2);
    cudaGetSymbolAddress((void**)&pPeB, g_peB);
    cudaGetSymbolAddress((void**)&pE, g_E);

    prep_kernel<<<1024, 256>>>(gru_wih, gru_whh, gru_bih, gru_bhh, conv_w, conv_b);

    sgemm_kernel<<<dim3(8, 2, 1), 256>>>(attn_w, conv_w, pW2 + 256 * CIN,
                                         256, CIN, H2, nullptr);
    sgemm_kernel<<<dim3(8, 2, 1), 256>>>(attn_w, pPeB, pE + 256 * LL,
                                         256, LL, H2, attn_b);
    gemb_kernel<<<dim3(CC, 4), 256>>>(emb);
    gcnt_kernel<<<dim3(BB, 4), 256>>>(count);
    mma_gemm_kernel<<<dim3(8, 4, BB), 256>>>(pW2, fm, pFh, pE);

    for (int t = 0; t < TT; t++) {
        score_kernel<<<dim3(9, BB), 256>>>(t, 8, count, attn_v, attn_vb,
                                           cov_w, cov_b, out_w, out_b, out);
        ctx_kernel<<<dim3(8, BB), 256>>>(t, target);
        gru_gemm_kernel<<<128, 256>>>();
    }
    score_kernel<<<dim3(1, BB), 256>>>(TT, 0, count, attn_v, attn_vb,
                                       cov_w, cov_b, out_w, out_b, out);
}

// round 12
// speedup vs baseline: 1.0592x; 1.0592x over previous
#include <cuda_runtime.h>
#include <cuda_bf16.h>
#include <math.h>
#include <stdint.h>

// ---------------- problem constants ----------------
#define BB   64
#define LL   1024
#define HH   256
#define H2   512
#define CC   111
#define TT   64
#define CIN  1024
#define DD   256
#define KCAT 879
#define NGI  1024
#define KX   623
#define XW   512        // xcat: [ctx(256) | h(256)]
#define GM   512
#define GN   1024
#define GK   1024

// ---------------- device scratch ----------------
__device__ __nv_bfloat16 g_Fh[(long)BB * H2 * LL];  // rows 0-255: ctx feats, 256-511: Wf
__device__ float g_scores[4 * BB * LL];
__device__ float g_cov[BB * LL];
__device__ float g_h[2 * BB * HH];
__device__ float g_context[BB * HH];
__device__ float g_gi[BB * NGI];
__device__ float g_xcat[BB * XW];
__device__ float g_WcatT[KCAT * NGI];   // rows: emb 0-255, ctx 256-511, cnt 512-622, h 623-878
__device__ float g_gbias[NGI];
__device__ float g_gemb[CC * NGI];
__device__ float g_gcntb[BB * NGI];
__device__ float g_W2[H2 * CIN];
__device__ float g_peB[H2 * LL];
__device__ float g_E[H2 * LL];
__device__ __nv_bfloat16 g_fmh[(long)BB * CIN * LL];
__device__ __nv_bfloat16 g_W2h[H2 * CIN];

__device__ __forceinline__ float ftanh(float x) {
    float y; asm("tanh.approx.f32 %0, %1;" : "=f"(y) : "f"(x)); return y;
}
__device__ __forceinline__ float pe_val(int l, int o) {
    float f = expf((float)(o & ~1) * (-9.210340371976184f / 512.f));
    float a = (float)l * f;
    return (o & 1) ? cosf(a) : sinf(a);
}
__device__ __forceinline__ uint32_t s2u(const void* p) {
    return (uint32_t)__cvta_generic_to_shared(p);
}
__device__ __forceinline__ void ldsm4(uint32_t* r, uint32_t a) {
    asm volatile("ldmatrix.sync.aligned.m8n8.x4.shared.b16 {%0,%1,%2,%3}, [%4];"
                 : "=r"(r[0]), "=r"(r[1]), "=r"(r[2]), "=r"(r[3]) : "r"(a));
}
__device__ __forceinline__ void ldsm4t(uint32_t* r, uint32_t a) {
    asm volatile("ldmatrix.sync.aligned.m8n8.x4.trans.shared.b16 {%0,%1,%2,%3}, [%4];"
                 : "=r"(r[0]), "=r"(r[1]), "=r"(r[2]), "=r"(r[3]) : "r"(a));
}
__device__ __forceinline__ void mma_bf16(float* d, const uint32_t* a, const uint32_t* b) {
    asm volatile(
        "mma.sync.aligned.m16n8k16.row.col.f32.bf16.bf16.f32 "
        "{%0,%1,%2,%3}, {%4,%5,%6,%7}, {%8,%9}, {%0,%1,%2,%3};\n"
        : "+f"(d[0]), "+f"(d[1]), "+f"(d[2]), "+f"(d[3])
        : "r"(a[0]), "r"(a[1]), "r"(a[2]), "r"(a[3]), "r"(b[0]), "r"(b[1]));
}

// ---------------- prep ----------------
__global__ void prep_kernel(const float* __restrict__ wih, const float* __restrict__ whh,
                            const float* __restrict__ bih, const float* __restrict__ bhh,
                            const float* __restrict__ convw, const float* __restrict__ convb) {
    const long R1 = (long)KCAT * NGI;
    const long R2 = R1 + NGI;
    const long R3 = R2 + 256L * CIN;
    const long R4 = R3 + (long)H2 * LL;
    const long R5 = R4 + 256L * LL;
    const long ZTOT = 2L*BB*HH + BB*LL + BB*HH + BB*XW;
    const long TOTAL = R5 + ZTOT;
    for (long idx = (long)blockIdx.x * blockDim.x + threadIdx.x; idx < TOTAL;
         idx += (long)gridDim.x * blockDim.x) {
        long i = idx;
        if (i < R1) {
            int k = (int)(i >> 10), j = (int)(i & 1023);
            float v = 0.f;
            if (j < 768) {
                if (k < KX) v = wih[j * KX + k];
                else if (j < 512) v = whh[j * HH + (k - KX)];
            } else {
                if (k >= KX) v = whh[(j - 768 + 512) * HH + (k - KX)];
            }
            g_WcatT[i] = v; continue;
        }
        if (i < R2) { int j = (int)(i - R1);
            g_gbias[j] = (j < 512) ? bih[j] + bhh[j] : (j < 768) ? bih[j] : bhh[j - 256];
            continue; }
        if (i < R3) { long p = i - R2; g_W2[p] = convw[p]; continue; }
        if (i < R4) { long p = i - R3; int o = (int)(p >> 10), l = (int)(p & 1023);
            g_peB[p] = pe_val(l, o) + convb[o]; continue; }
        if (i < R5) { long p = i - R4; int m = (int)(p >> 10), l = (int)(p & 1023);
            g_E[p] = convb[m] + pe_val(l, m); continue; }
        long p = i - R5;
        if (p < 2L*BB*HH) { g_h[p] = 0.f; continue; } p -= 2L*BB*HH;
        if (p < BB*LL) { g_cov[p] = 0.f; continue; } p -= BB*LL;
        if (p < BB*HH) { g_context[p] = 0.f; continue; } p -= BB*HH;
        g_xcat[p] = 0.f;
    }
}

// ---------------- precompute gemb[c] = emb[c] @ Wemb ----------------
__global__ __launch_bounds__(256) void gemb_kernel(const float* __restrict__ emb) {
    const int c = blockIdx.x, tid = threadIdx.x;
    __shared__ float s_e[DD];
    s_e[tid] = emb[c * DD + tid];
    __syncthreads();
    const int j0 = tid * 4;
    float4 acc = make_float4(0.f, 0.f, 0.f, 0.f);
#pragma unroll 8
    for (int k = 0; k < DD; k++) {
        float4 w = *(const float4*)&g_WcatT[(long)k * NGI + j0];
        float e = s_e[k];
        acc.x = fmaf(e, w.x, acc.x); acc.y = fmaf(e, w.y, acc.y);
        acc.z = fmaf(e, w.z, acc.z); acc.w = fmaf(e, w.w, acc.w);
    }
    *(float4*)&g_gemb[(long)c * NGI + j0] = acc;
}

// ---------------- precompute gcntb[b] = gbias + count[b] @ Wcnt ----------------
__global__ __launch_bounds__(256) void gcnt_kernel(const float* __restrict__ count) {
    const int b = blockIdx.x, tid = threadIdx.x;
    __shared__ float s_c[CC];
    if (tid < CC) s_c[tid] = count[b * CC + tid];
    __syncthreads();
    const int j0 = tid * 4;
    float4 acc = *(const float4*)&g_gbias[j0];
#pragma unroll 8
    for (int k = 0; k < CC; k++) {
        float4 w = *(const float4*)&g_WcatT[(long)(512 + k) * NGI + j0];
        float e = s_c[k];
        acc.x = fmaf(e, w.x, acc.x); acc.y = fmaf(e, w.y, acc.y);
        acc.z = fmaf(e, w.z, acc.z); acc.w = fmaf(e, w.w, acc.w);
    }
    *(float4*)&g_gcntb[(long)b * NGI + j0] = acc;
}

// ---------------- SIMT SGEMM (small prep GEMMs only) ----------------
__global__ __launch_bounds__(256, 2) void sgemm_kernel(
    const float* __restrict__ A, const float* __restrict__ Bg, float* __restrict__ Cg,
    int M, int N, int K, const float* __restrict__ bias) {
    const int bx = blockIdx.x, by = blockIdx.y, b = blockIdx.z;
    const float* Bp = Bg + (long)b * K * N;
    float* Cp = Cg + (long)b * M * N;
    const int tid = threadIdx.x;
    __shared__ float As[8][128];
    __shared__ float Bs[8][128];
    float acc[8][8];
#pragma unroll
    for (int i = 0; i < 8; i++)
#pragma unroll
        for (int j = 0; j < 8; j++) acc[i][j] = 0.f;
    const int m0 = by * 128, n0 = bx * 128;
    const int arow = tid >> 1, acol = (tid & 1) * 4;
    const int brow = tid >> 5, bcol = (tid & 31) * 4;
    const int ty = tid >> 4, tx = tid & 15;
    for (int k0 = 0; k0 < K; k0 += 8) {
        float4 a4 = *(const float4*)&A[(long)(m0 + arow) * K + k0 + acol];
        As[acol + 0][arow] = a4.x; As[acol + 1][arow] = a4.y;
        As[acol + 2][arow] = a4.z; As[acol + 3][arow] = a4.w;
        *(float4*)&Bs[brow][bcol] = *(const float4*)&Bp[(long)(k0 + brow) * N + n0 + bcol];
        __syncthreads();
#pragma unroll
        for (int kk = 0; kk < 8; kk++) {
            float ra[8], rb[8];
#pragma unroll
            for (int i = 0; i < 8; i++) ra[i] = As[kk][ty * 8 + i];
#pragma unroll
            for (int j = 0; j < 8; j++) rb[j] = Bs[kk][tx * 8 + j];
#pragma unroll
            for (int i = 0; i < 8; i++)
#pragma unroll
                for (int j = 0; j < 8; j++) acc[i][j] = fmaf(ra[i], rb[j], acc[i][j]);
        }
        __syncthreads();
    }
#pragma unroll
    for (int i = 0; i < 8; i++) {
        int m = m0 + ty * 8 + i;
        float bia = bias ? bias[m] : 0.f;
#pragma unroll
        for (int j = 0; j < 8; j++)
            Cp[(long)m * N + n0 + tx * 8 + j] = acc[i][j] + bia;
    }
}

// ---------------- fp32 -> bf16 conversion ----------------
__global__ void cvt_kernel(const float* __restrict__ fm) {
    const long N1 = (long)BB * CIN * LL / 4;
    const long N2 = (long)H2 * CIN / 4;
    __nv_bfloat162* fo = (__nv_bfloat162*)g_fmh;
    __nv_bfloat162* wo = (__nv_bfloat162*)g_W2h;
    for (long i = (long)blockIdx.x * blockDim.x + threadIdx.x; i < N1 + N2;
         i += (long)gridDim.x * blockDim.x) {
        if (i < N1) {
            float4 v = ((const float4*)fm)[i];
            fo[2 * i]     = __floats2bfloat162_rn(v.x, v.y);
            fo[2 * i + 1] = __floats2bfloat162_rn(v.z, v.w);
        } else {
            long j = i - N1;
            float4 v = ((const float4*)g_W2)[j];
            wo[2 * j]     = __floats2bfloat162_rn(v.x, v.y);
            wo[2 * j + 1] = __floats2bfloat162_rn(v.z, v.w);
        }
    }
}

// ---------------- bf16 tensor-core main GEMM, bf16 output ----------------
__global__ __launch_bounds__(256, 2) void mma_gemm_kernel(
    const __nv_bfloat16* __restrict__ A, const __nv_bfloat16* __restrict__ Bg,
    __nv_bfloat16* __restrict__ Cg, const float* __restrict__ Etab) {
    const int tid = threadIdx.x;
    const int bx = blockIdx.x, by = blockIdx.y, b = blockIdx.z;
    const __nv_bfloat16* Bp = Bg + (long)b * GK * GN;
    __nv_bfloat16* Cp = Cg + (long)b * GM * GN;
    __shared__ __nv_bfloat16 As[128][40];
    __shared__ __nv_bfloat16 Bs[32][136];
    const int w = tid >> 5, lane = tid & 31;
    const int wm = (w & 3) * 32, wn = (w >> 2) * 64;
    const int m0 = by * 128, n0 = bx * 128;
    const int lg = lane >> 2, lk = lane & 3;

    float acc[2][8][4];
#pragma unroll
    for (int i = 0; i < 2; i++)
#pragma unroll
        for (int j = 0; j < 8; j++)
#pragma unroll
            for (int c = 0; c < 4; c++) acc[i][j][c] = 0.f;

    const int ar = tid >> 1, ac = (tid & 1) * 16;
    const int br = tid >> 3, bc = (tid & 7) * 16;
    const uint32_t aAddr0 = s2u(&As[wm + (lane & 15)][(lane >> 4) * 8]);
    const uint32_t bAddr0 = s2u(&Bs[lane & 15][wn + (lane >> 4) * 8]);

    uint4 ra0, ra1, rb0, rb1;
    {
        const uint4* pa = (const uint4*)(A + (long)(m0 + ar) * GK + ac);
        const uint4* pb = (const uint4*)(Bp + (long)br * GN + n0 + bc);
        ra0 = pa[0]; ra1 = pa[1];
        rb0 = pb[0]; rb1 = pb[1];
    }

    for (int kt = 0; kt < GK / 32; kt++) {
        *(uint4*)&As[ar][ac]     = ra0;
        *(uint4*)&As[ar][ac + 8] = ra1;
        *(uint4*)&Bs[br][bc]     = rb0;
        *(uint4*)&Bs[br][bc + 8] = rb1;
        __syncthreads();
        if (kt + 1 < GK / 32) {
            int k0 = (kt + 1) * 32;
            const uint4* pa = (const uint4*)(A + (long)(m0 + ar) * GK + k0 + ac);
            const uint4* pb = (const uint4*)(Bp + (long)(k0 + br) * GN + n0 + bc);
            ra0 = pa[0]; ra1 = pa[1];
            rb0 = pb[0]; rb1 = pb[1];
        }
#pragma unroll
        for (int ks = 0; ks < 2; ks++) {
            uint32_t af[2][4], bf[4][4];
#pragma unroll
            for (int tm = 0; tm < 2; tm++)
                ldsm4(af[tm], aAddr0 + (tm * 16 * 40 + ks * 16) * 2);
#pragma unroll
            for (int p = 0; p < 4; p++)
                ldsm4t(bf[p], bAddr0 + (ks * 16 * 136 + p * 16) * 2);
#pragma unroll
            for (int tn = 0; tn < 8; tn++) {
                mma_bf16(acc[0][tn], af[0], &bf[tn >> 1][(tn & 1) * 2]);
                mma_bf16(acc[1][tn], af[1], &bf[tn >> 1][(tn & 1) * 2]);
            }
        }
        __syncthreads();
    }
#pragma unroll
    for (int tm = 0; tm < 2; tm++) {
#pragma unroll
        for (int tn = 0; tn < 8; tn++) {
            int m = m0 + wm + tm * 16 + lg;
            int n = n0 + wn + tn * 8 + 2 * lk;
            long i0 = (long)m * GN + n;
            long i1 = (long)(m + 8) * GN + n;
            float2 e0 = *(const float2*)&Etab[i0];
            float2 e1 = *(const float2*)&Etab[i1];
            *(__nv_bfloat162*)(Cp + i0) =
                __floats2bfloat162_rn(acc[tm][tn][0] + e0.x, acc[tm][tn][1] + e0.y);
            *(__nv_bfloat162*)(Cp + i1) =
                __floats2bfloat162_rn(acc[tm][tn][2] + e1.x, acc[tm][tn][3] + e1.y);
        }
    }
}

// ---------------- K1: gate finalize + out_{t-1} + attention score partials ----------
__global__ __launch_bounds__(256) void score_kernel(
    int t, int nch,
    const float* __restrict__ count,
    const float* __restrict__ attn_v, const float* __restrict__ attn_vb,
    const float* __restrict__ cov_w, const float* __restrict__ cov_b,
    const float* __restrict__ out_w, const float* __restrict__ out_b,
    float* __restrict__ d_out) {
    const int b = blockIdx.y, cx = blockIdx.x, tid = threadIdx.x;
    float hn = 0.f;
    if (t > 0) {
        const float* gi = g_gi + b * NGI;
        float gr = gi[tid], gz = gi[256 + tid], gin = gi[512 + tid], ghn = gi[768 + tid];
        float hold = g_h[((t - 1) & 1) * BB * HH + b * HH + tid];
        float r = 1.f / (1.f + expf(-gr));
        float z = 1.f / (1.f + expf(-gz));
        float n = tanhf(gin + r * ghn);
        hn = (1.f - z) * n + z * hold;
    }

    if (cx == nch) {  // aux block: h_t, xcat h-part, out_{t-1}
        __shared__ float s_x2[640];
        g_h[(t & 1) * BB * HH + b * HH + tid] = hn;
        if (t < TT) g_xcat[b * XW + 256 + tid] = hn;
        if (t > 0) {
            s_x2[tid] = hn;
            s_x2[256 + tid] = g_context[b * HH + tid];
            if (tid < CC) s_x2[512 + tid] = count[b * CC + tid];
            __syncthreads();
            const int warp = tid >> 5, lane = tid & 31;
            float* op = d_out + ((long)b * TT + (t - 1)) * CC;
#pragma unroll
            for (int i = 0; i < 14; i++) {
                int c = warp * 14 + i;
                if (c < CC) {
                    const float* wrow = out_w + (long)c * KX;
                    float acc = 0.f;
                    for (int k = lane; k < KX; k += 32)
                        acc = fmaf(wrow[k], s_x2[k], acc);
#pragma unroll
                    for (int o = 16; o > 0; o >>= 1)
                        acc += __shfl_xor_sync(0xffffffffu, acc, o);
                    if (lane == 0) op[c] = acc + out_b[c];
                }
            }
        }
        return;
    }

    const int lchunk = cx & 1, hq = cx >> 1, hh0 = hq * 64;
    __shared__ float s_hfull[HH];
    __shared__ float s_base[64], s_cw[64], s_v[64];
    s_hfull[tid] = hn;
    __syncthreads();
    if (tid < 64) {
        int h = hh0 + tid;
        s_base[tid] = cov_b[h] + s_hfull[h];
        s_cw[tid] = cov_w[h];
        s_v[tid] = attn_v[h];
    }
    __syncthreads();

    const int p = lchunk * 256 + tid;
    const float2 cov = *(const float2*)&g_cov[b * LL + 2 * p];
    const __nv_bfloat162* wf2 =
        (const __nv_bfloat162*)(g_Fh + ((long)b * H2 + 256 + hh0) * LL) + p;
    float a0 = (hq == 0) ? attn_vb[0] : 0.f, a1 = 0.f;
    float b0 = 0.f, b1 = 0.f;
#pragma unroll 8
    for (int hh = 0; hh < 64; hh += 2) {
        float2 w0 = __bfloat1622float2(wf2[(long)hh * 512]);
        float2 w1 = __bfloat1622float2(wf2[(long)(hh + 1) * 512]);
        float ba0 = s_base[hh], cw0 = s_cw[hh], vv0 = s_v[hh];
        float ba1 = s_base[hh + 1], cw1 = s_cw[hh + 1], vv1 = s_v[hh + 1];
        a0 = fmaf(vv0, ftanh(fmaf(cov.x, cw0, w0.x + ba0)), a0);
        a1 = fmaf(vv0, ftanh(fmaf(cov.y, cw0, w0.y + ba0)), a1);
        b0 = fmaf(vv1, ftanh(fmaf(cov.x, cw1, w1.x + ba1)), b0);
        b1 = fmaf(vv1, ftanh(fmaf(cov.y, cw1, w1.y + ba1)), b1);
    }
    *(float2*)&g_scores[hq * BB * LL + b * LL + 2 * p] = make_float2(a0 + b0, a1 + b1);
}

// ---------------- K2: softmax + coverage + context + xcat ctx-part + gi init ------
__global__ __launch_bounds__(256) void ctx_kernel(int t, const int* __restrict__ target) {
    const int b = blockIdx.y, c = blockIdx.x, tid = threadIdx.x;
    const int warp = tid >> 5, lane = tid & 31;
    __shared__ float s_alpha[LL];
    __shared__ float s_red[8];

    float4 p0 = ((const float4*)(g_scores + b * LL))[tid];
    float4 p1 = ((const float4*)(g_scores + 1 * BB * LL + b * LL))[tid];
    float4 p2 = ((const float4*)(g_scores + 2 * BB * LL + b * LL))[tid];
    float4 p3 = ((const float4*)(g_scores + 3 * BB * LL + b * LL))[tid];
    float4 sc = make_float4((p0.x + p1.x) + (p2.x + p3.x),
                            (p0.y + p1.y) + (p2.y + p3.y),
                            (p0.z + p1.z) + (p2.z + p3.z),
                            (p0.w + p1.w) + (p2.w + p3.w));
    float mx = fmaxf(fmaxf(sc.x, sc.y), fmaxf(sc.z, sc.w));
#pragma unroll
    for (int o = 16; o > 0; o >>= 1) mx = fmaxf(mx, __shfl_xor_sync(0xffffffffu, mx, o));
    if (lane == 0) s_red[warp] = mx;
    __syncthreads();
    float M = s_red[0];
#pragma unroll
    for (int w = 1; w < 8; w++) M = fmaxf(M, s_red[w]);
    float e0 = __expf(sc.x - M), e1 = __expf(sc.y - M);
    float e2 = __expf(sc.z - M), e3 = __expf(sc.w - M);
    float sm = e0 + e1 + e2 + e3;
#pragma unroll
    for (int o = 16; o > 0; o >>= 1) sm += __shfl_xor_sync(0xffffffffu, sm, o);
    __syncthreads();
    if (lane == 0) s_red[warp] = sm;
    __syncthreads();
    float S = 0.f;
#pragma unroll
    for (int w = 0; w < 8; w++) S += s_red[w];
    float inv = 1.f / S;
    float4 al = make_float4(e0 * inv, e1 * inv, e2 * inv, e3 * inv);
    ((float4*)s_alpha)[tid] = al;
    if (c == 0) {
        float4 cv = ((float4*)(g_cov + b * LL))[tid];
        cv.x += al.x; cv.y += al.y; cv.z += al.z; cv.w += al.w;
        ((float4*)(g_cov + b * LL))[tid] = cv;
    }
    __syncthreads();

    const __nv_bfloat16* fb = g_Fh + (long)b * H2 * LL;
#pragma unroll
    for (int r = 0; r < 4; r++) {
        int d = c * 32 + warp * 4 + r;
        const uint4* row = (const uint4*)(fb + (long)d * LL);
        float sum = 0.f;
#pragma unroll
        for (int it = 0; it < 4; it++) {
            uint4 f8 = row[it * 32 + lane];
            const float4* ap = (const float4*)&s_alpha[(it * 32 + lane) * 8];
            float4 a0 = ap[0], a1 = ap[1];
            float2 f0 = __bfloat1622float2(*(__nv_bfloat162*)&f8.x);
            float2 f1 = __bfloat1622float2(*(__nv_bfloat162*)&f8.y);
            float2 f2 = __bfloat1622float2(*(__nv_bfloat162*)&f8.z);
            float2 f3 = __bfloat1622float2(*(__nv_bfloat162*)&f8.w);
            sum = fmaf(f0.x, a0.x, sum); sum = fmaf(f0.y, a0.y, sum);
            sum = fmaf(f1.x, a0.z, sum); sum = fmaf(f1.y, a0.w, sum);
            sum = fmaf(f2.x, a1.x, sum); sum = fmaf(f2.y, a1.y, sum);
            sum = fmaf(f3.x, a1.z, sum); sum = fmaf(f3.y, a1.w, sum);
        }
#pragma unroll
        for (int o = 16; o > 0; o >>= 1) sum += __shfl_xor_sync(0xffffffffu, sum, o);
        if (lane == 0) {
            g_context[b * HH + d] = sum;
            g_xcat[b * XW + d] = sum;
        }
    }

    if (tid < 128) {
        int y = (t == 0) ? 1 : target[b * TT + (t - 1)];
        int j = c * 128 + tid;
        g_gi[b * NGI + j] = g_gemb[(long)y * NGI + j] + g_gcntb[(long)b * NGI + j];
    }
}

// ---------------- K3: GRU gate GEMM, K=512 ([ctx|h]), K-split atomic ----------------
__global__ __launch_bounds__(256) void gru_gemm_kernel() {
    const int nt = blockIdx.x & 15, ks = blockIdx.x >> 4;
    const int n0 = nt * 64, k0 = ks * 64;
    const int tid = threadIdx.x;
    __shared__ float Xs[16][68];
    __shared__ float Ws[16][64];
    const int ml = tid >> 2, kq = (tid & 3) * 4;
    const int kw = tid >> 4, nn = (tid & 15) * 4;
    const int ty = tid >> 4, tx = tid & 15;
    float acc[4][4];
#pragma unroll
    for (int i = 0; i < 4; i++)
#pragma unroll
        for (int j = 0; j < 4; j++) acc[i][j] = 0.f;

#pragma unroll
    for (int kt = 0; kt < 4; kt++) {
        const int k = k0 + kt * 16;
        float4 x4 = *(const float4*)&g_xcat[ml * XW + k + kq];
        Xs[kq + 0][ml] = x4.x; Xs[kq + 1][ml] = x4.y;
        Xs[kq + 2][ml] = x4.z; Xs[kq + 3][ml] = x4.w;
        const int row = (k < 256) ? (256 + k + kw) : (623 + (k - 256) + kw);
        *(float4*)&Ws[kw][nn] = *(const float4*)&g_WcatT[(long)row * NGI + n0 + nn];
        __syncthreads();
#pragma unroll
        for (int kk = 0; kk < 16; kk++) {
            float rx[4], rw[4];
#pragma unroll
            for (int i = 0; i < 4; i++) rx[i] = Xs[kk][ty * 4 + i];
#pragma unroll
            for (int j = 0; j < 4; j++) rw[j] = Ws[kk][tx * 4 + j];
#pragma unroll
            for (int i = 0; i < 4; i++)
#pragma unroll
                for (int j = 0; j < 4; j++) acc[i][j] = fmaf(rx[i], rw[j], acc[i][j]);
        }
        __syncthreads();
    }
#pragma unroll
    for (int i = 0; i < 4; i++)
#pragma unroll
        for (int j = 0; j < 4; j++)
            atomicAdd(&g_gi[(ty * 4 + i) * NGI + n0 + tx * 4 + j], acc[i][j]);
}

// ---------------- launch ----------------
extern "C" void kernel_launch(void* const* d_in, const int* in_sizes, int n_in,
                              void* d_out, int out_size) {
    const float* fm      = (const float*)d_in[0];
    const float* count   = (const float*)d_in[1];
    const int*   target  = (const int*)d_in[2];
    const float* conv_w  = (const float*)d_in[3];
    const float* conv_b  = (const float*)d_in[4];
    const float* emb     = (const float*)d_in[5];
    const float* gru_wih = (const float*)d_in[6];
    const float* gru_whh = (const float*)d_in[7];
    const float* gru_bih = (const float*)d_in[8];
    const float* gru_bhh = (const float*)d_in[9];
    const float* attn_w  = (const float*)d_in[10];
    const float* attn_b  = (const float*)d_in[11];
    const float* attn_v  = (const float*)d_in[12];
    const float* attn_vb = (const float*)d_in[13];
    const float* cov_w   = (const float*)d_in[14];
    const float* cov_b   = (const float*)d_in[15];
    const float* out_w   = (const float*)d_in[16];
    const float* out_b   = (const float*)d_in[17];
    float* out = (float*)d_out;

    float *pW2, *pPeB, *pE;
    __nv_bfloat16 *pFh, *pFmh, *pW2h;
    cudaGetSymbolAddress((void**)&pFh, g_Fh);
    cudaGetSymbolAddress((void**)&pW2, g_W2);
    cudaGetSymbolAddress((void**)&pPeB, g_peB);
    cudaGetSymbolAddress((void**)&pE, g_E);
    cudaGetSymbolAddress((void**)&pFmh, g_fmh);
    cudaGetSymbolAddress((void**)&pW2h, g_W2h);

    // once-only side stream + events for captured fork/join
    static cudaStream_t s1 = nullptr;
    static cudaEvent_t evFork = nullptr, evJoin = nullptr;
    if (!s1) {
        cudaStreamCreateWithFlags(&s1, cudaStreamNonBlocking);
        cudaEventCreateWithFlags(&evFork, cudaEventDisableTiming);
        cudaEventCreateWithFlags(&evJoin, cudaEventDisableTiming);
    }
    // main (captured) stream is the legacy default stream for <<<>>> launches
    cudaStream_t s0 = (cudaStream_t)0;

    prep_kernel<<<1024, 256>>>(gru_wih, gru_whh, gru_bih, gru_bhh, conv_w, conv_b);
    cudaEventRecord(evFork, s0);

    // side stream: gate-precompute (depends only on prep's WcatT/gbias)
    cudaStreamWaitEvent(s1, evFork, 0);
    gemb_kernel<<<CC, 256, 0, s1>>>(emb);
    gcnt_kernel<<<BB, 256, 0, s1>>>(count);
    cudaEventRecord(evJoin, s1);

    // main stream: feature pipeline
    sgemm_kernel<<<dim3(8, 2, 1), 256>>>(attn_w, conv_w, pW2 + 256 * CIN,
                                         256, CIN, H2, nullptr);
    sgemm_kernel<<<dim3(8, 2, 1), 256>>>(attn_w, pPeB, pE + 256 * LL,
                                         256, LL, H2, attn_b);
    cvt_kernel<<<2048, 256>>>(fm);
    mma_gemm_kernel<<<dim3(8, 4, BB), 256>>>(pW2h, pFmh, pFh, pE);
    cudaStreamWaitEvent(s0, evJoin, 0);

    for (int t = 0; t < TT; t++) {
        score_kernel<<<dim3(9, BB), 256>>>(t, 8, count, attn_v, attn_vb,
                                           cov_w, cov_b, out_w, out_b, out);
        ctx_kernel<<<dim3(8, BB), 256>>>(t, target);
        gru_gemm_kernel<<<128, 256>>>();
    }
    score_kernel<<<dim3(1, BB), 256>>>(TT, 0, count, attn_v, attn_vb,
                                       cov_w, cov_b, out_w, out_b, out);
}

// round 14
// speedup vs baseline: 1.1147x; 1.0523x over previous
#include <cuda_runtime.h>
#include <cuda_bf16.h>
#include <math.h>
#include <stdint.h>

// ---------------- problem constants ----------------
#define BB   64
#define LL   1024
#define HH   256
#define H2   512
#define CC   111
#define TT   64
#define CIN  1024
#define DD   256
#define KCAT 879
#define NGI  1024
#define KX   623
#define XW   512        // xcat: [ctx(256) | h(256)]
#define GM   512
#define GN   1024
#define GK   1024

// ---------------- device scratch ----------------
__device__ __nv_bfloat16 g_Fh[(long)BB * H2 * LL];  // rows 0-255: ctx feats, 256-511: Wf
__device__ float g_scores[4 * BB * LL];
__device__ float g_cov[BB * LL];
__device__ float g_h[2 * BB * HH];
__device__ float g_context[BB * HH];
__device__ float g_gi[BB * NGI];
__device__ float g_xcat[BB * XW];
__device__ float g_WcatT[KCAT * NGI];   // rows: emb 0-255, ctx 256-511, cnt 512-622, h 623-878
__device__ float g_gbias[NGI];
__device__ float g_gemb[CC * NGI];
__device__ float g_gcntb[BB * NGI];
__device__ float g_W2[H2 * CIN];
__device__ float g_peB[H2 * LL];
__device__ float g_E[H2 * LL];
__device__ __nv_bfloat16 g_fmh[(long)BB * CIN * LL];
__device__ __nv_bfloat16 g_W2h[H2 * CIN];

__device__ __forceinline__ float ftanh(float x) {
    float y; asm("tanh.approx.f32 %0, %1;" : "=f"(y) : "f"(x)); return y;
}
__device__ __forceinline__ float pe_val(int l, int o) {
    float f = expf((float)(o & ~1) * (-9.210340371976184f / 512.f));
    float a = (float)l * f;
    return (o & 1) ? cosf(a) : sinf(a);
}
__device__ __forceinline__ uint32_t s2u(const void* p) {
    return (uint32_t)__cvta_generic_to_shared(p);
}
__device__ __forceinline__ void ldsm4(uint32_t* r, uint32_t a) {
    asm volatile("ldmatrix.sync.aligned.m8n8.x4.shared.b16 {%0,%1,%2,%3}, [%4];"
                 : "=r"(r[0]), "=r"(r[1]), "=r"(r[2]), "=r"(r[3]) : "r"(a));
}
__device__ __forceinline__ void ldsm4t(uint32_t* r, uint32_t a) {
    asm volatile("ldmatrix.sync.aligned.m8n8.x4.trans.shared.b16 {%0,%1,%2,%3}, [%4];"
                 : "=r"(r[0]), "=r"(r[1]), "=r"(r[2]), "=r"(r[3]) : "r"(a));
}
__device__ __forceinline__ void mma_bf16(float* d, const uint32_t* a, const uint32_t* b) {
    asm volatile(
        "mma.sync.aligned.m16n8k16.row.col.f32.bf16.bf16.f32 "
        "{%0,%1,%2,%3}, {%4,%5,%6,%7}, {%8,%9}, {%0,%1,%2,%3};\n"
        : "+f"(d[0]), "+f"(d[1]), "+f"(d[2]), "+f"(d[3])
        : "r"(a[0]), "r"(a[1]), "r"(a[2]), "r"(a[3]), "r"(b[0]), "r"(b[1]));
}

// ---------------- prep ----------------
__global__ void prep_kernel(const float* __restrict__ wih, const float* __restrict__ whh,
                            const float* __restrict__ bih, const float* __restrict__ bhh,
                            const float* __restrict__ convw, const float* __restrict__ convb) {
    const long R1 = (long)KCAT * NGI;
    const long R2 = R1 + NGI;
    const long R3 = R2 + 256L * CIN;
    const long R4 = R3 + (long)H2 * LL;
    const long R5 = R4 + 256L * LL;
    const long ZTOT = 2L*BB*HH + BB*LL + BB*HH + BB*XW;
    const long TOTAL = R5 + ZTOT;
    for (long idx = (long)blockIdx.x * blockDim.x + threadIdx.x; idx < TOTAL;
         idx += (long)gridDim.x * blockDim.x) {
        long i = idx;
        if (i < R1) {
            int k = (int)(i >> 10), j = (int)(i & 1023);
            float v = 0.f;
            if (j < 768) {
                if (k < KX) v = wih[j * KX + k];
                else if (j < 512) v = whh[j * HH + (k - KX)];
            } else {
                if (k >= KX) v = whh[(j - 768 + 512) * HH + (k - KX)];
            }
            g_WcatT[i] = v; continue;
        }
        if (i < R2) { int j = (int)(i - R1);
            g_gbias[j] = (j < 512) ? bih[j] + bhh[j] : (j < 768) ? bih[j] : bhh[j - 256];
            continue; }
        if (i < R3) { long p = i - R2; g_W2[p] = convw[p]; continue; }
        if (i < R4) { long p = i - R3; int o = (int)(p >> 10), l = (int)(p & 1023);
            g_peB[p] = pe_val(l, o) + convb[o]; continue; }
        if (i < R5) { long p = i - R4; int m = (int)(p >> 10), l = (int)(p & 1023);
            g_E[p] = convb[m] + pe_val(l, m); continue; }
        long p = i - R5;
        if (p < 2L*BB*HH) { g_h[p] = 0.f; continue; } p -= 2L*BB*HH;
        if (p < BB*LL) { g_cov[p] = 0.f; continue; } p -= BB*LL;
        if (p < BB*HH) { g_context[p] = 0.f; continue; } p -= BB*HH;
        g_xcat[p] = 0.f;
    }
}

// ---------------- precompute gemb[c] = emb[c] @ Wemb ----------------
__global__ __launch_bounds__(256) void gemb_kernel(const float* __restrict__ emb) {
    const int c = blockIdx.x, tid = threadIdx.x;
    __shared__ float s_e[DD];
    s_e[tid] = emb[c * DD + tid];
    __syncthreads();
    const int j0 = tid * 4;
    float4 acc = make_float4(0.f, 0.f, 0.f, 0.f);
#pragma unroll 8
    for (int k = 0; k < DD; k++) {
        float4 w = *(const float4*)&g_WcatT[(long)k * NGI + j0];
        float e = s_e[k];
        acc.x = fmaf(e, w.x, acc.x); acc.y = fmaf(e, w.y, acc.y);
        acc.z = fmaf(e, w.z, acc.z); acc.w = fmaf(e, w.w, acc.w);
    }
    *(float4*)&g_gemb[(long)c * NGI + j0] = acc;
}

// ---------------- precompute gcntb[b] = gbias + count[b] @ Wcnt ----------------
__global__ __launch_bounds__(256) void gcnt_kernel(const float* __restrict__ count) {
    const int b = blockIdx.x, tid = threadIdx.x;
    __shared__ float s_c[CC];
    if (tid < CC) s_c[tid] = count[b * CC + tid];
    __syncthreads();
    const int j0 = tid * 4;
    float4 acc = *(const float4*)&g_gbias[j0];
#pragma unroll 8
    for (int k = 0; k < CC; k++) {
        float4 w = *(const float4*)&g_WcatT[(long)(512 + k) * NGI + j0];
        float e = s_c[k];
        acc.x = fmaf(e, w.x, acc.x); acc.y = fmaf(e, w.y, acc.y);
        acc.z = fmaf(e, w.z, acc.z); acc.w = fmaf(e, w.w, acc.w);
    }
    *(float4*)&g_gcntb[(long)b * NGI + j0] = acc;
}

// ---------------- 64x64-tile SGEMM (small prep GEMMs, wide grid) ----------------
// C(M,N) = A(M,K) @ B(K,N) [+bias[m]]; grid (N/64, M/64)
__global__ __launch_bounds__(256) void sgemm64_kernel(
    const float* __restrict__ A, const float* __restrict__ B, float* __restrict__ C,
    int M, int N, int K, const float* __restrict__ bias) {
    const int tid = threadIdx.x;
    const int n0 = blockIdx.x * 64, m0 = blockIdx.y * 64;
    __shared__ float As[16][64];
    __shared__ float Bs[16][68];
    const int ty = tid >> 4, tx = tid & 15;
    const int arow = tid >> 2, acol = (tid & 3) * 4;
    const int brow = tid >> 4, bcol = (tid & 15) * 4;
    float acc[4][4];
#pragma unroll
    for (int i = 0; i < 4; i++)
#pragma unroll
        for (int j = 0; j < 4; j++) acc[i][j] = 0.f;

    for (int k0 = 0; k0 < K; k0 += 16) {
        float4 a4 = *(const float4*)&A[(long)(m0 + arow) * K + k0 + acol];
        As[acol + 0][arow] = a4.x; As[acol + 1][arow] = a4.y;
        As[acol + 2][arow] = a4.z; As[acol + 3][arow] = a4.w;
        *(float4*)&Bs[brow][bcol] = *(const float4*)&B[(long)(k0 + brow) * N + n0 + bcol];
        __syncthreads();
#pragma unroll
        for (int kk = 0; kk < 16; kk++) {
            float ra[4], rb[4];
#pragma unroll
            for (int i = 0; i < 4; i++) ra[i] = As[kk][ty * 4 + i];
#pragma unroll
            for (int j = 0; j < 4; j++) rb[j] = Bs[kk][tx * 4 + j];
#pragma unroll
            for (int i = 0; i < 4; i++)
#pragma unroll
                for (int j = 0; j < 4; j++) acc[i][j] = fmaf(ra[i], rb[j], acc[i][j]);
        }
        __syncthreads();
    }
#pragma unroll
    for (int i = 0; i < 4; i++) {
        int m = m0 + ty * 4 + i;
        float bia = bias ? bias[m] : 0.f;
#pragma unroll
        for (int j = 0; j < 4; j++)
            C[(long)m * N + n0 + tx * 4 + j] = acc[i][j] + bia;
    }
}

// ---------------- fp32 -> bf16: feature map only (no deps) ----------------
__global__ void cvt_fm_kernel(const float* __restrict__ fm) {
    const long N1 = (long)BB * CIN * LL / 4;
    __nv_bfloat162* fo = (__nv_bfloat162*)g_fmh;
    for (long i = (long)blockIdx.x * blockDim.x + threadIdx.x; i < N1;
         i += (long)gridDim.x * blockDim.x) {
        float4 v = ((const float4*)fm)[i];
        fo[2 * i]     = __floats2bfloat162_rn(v.x, v.y);
        fo[2 * i + 1] = __floats2bfloat162_rn(v.z, v.w);
    }
}

// ---------------- fp32 -> bf16: W2 (after its bottom half is computed) ----------------
__global__ void cvt_w2_kernel() {
    const long N2 = (long)H2 * CIN / 4;
    __nv_bfloat162* wo = (__nv_bfloat162*)g_W2h;
    for (long j = (long)blockIdx.x * blockDim.x + threadIdx.x; j < N2;
         j += (long)gridDim.x * blockDim.x) {
        float4 v = ((const float4*)g_W2)[j];
        wo[2 * j]     = __floats2bfloat162_rn(v.x, v.y);
        wo[2 * j + 1] = __floats2bfloat162_rn(v.z, v.w);
    }
}

// ---------------- bf16 tensor-core main GEMM, bf16 output ----------------
__global__ __launch_bounds__(256, 2) void mma_gemm_kernel(
    const __nv_bfloat16* __restrict__ A, const __nv_bfloat16* __restrict__ Bg,
    __nv_bfloat16* __restrict__ Cg, const float* __restrict__ Etab) {
    const int tid = threadIdx.x;
    const int bx = blockIdx.x, by = blockIdx.y, b = blockIdx.z;
    const __nv_bfloat16* Bp = Bg + (long)b * GK * GN;
    __nv_bfloat16* Cp = Cg + (long)b * GM * GN;
    __shared__ __nv_bfloat16 As[128][40];
    __shared__ __nv_bfloat16 Bs[32][136];
    const int w = tid >> 5, lane = tid & 31;
    const int wm = (w & 3) * 32, wn = (w >> 2) * 64;
    const int m0 = by * 128, n0 = bx * 128;
    const int lg = lane >> 2, lk = lane & 3;

    float acc[2][8][4];
#pragma unroll
    for (int i = 0; i < 2; i++)
#pragma unroll
        for (int j = 0; j < 8; j++)
#pragma unroll
            for (int c = 0; c < 4; c++) acc[i][j][c] = 0.f;

    const int ar = tid >> 1, ac = (tid & 1) * 16;
    const int br = tid >> 3, bc = (tid & 7) * 16;
    const uint32_t aAddr0 = s2u(&As[wm + (lane & 15)][(lane >> 4) * 8]);
    const uint32_t bAddr0 = s2u(&Bs[lane & 15][wn + (lane >> 4) * 8]);

    uint4 ra0, ra1, rb0, rb1;
    {
        const uint4* pa = (const uint4*)(A + (long)(m0 + ar) * GK + ac);
        const uint4* pb = (const uint4*)(Bp + (long)br * GN + n0 + bc);
        ra0 = pa[0]; ra1 = pa[1];
        rb0 = pb[0]; rb1 = pb[1];
    }

    for (int kt = 0; kt < GK / 32; kt++) {
        *(uint4*)&As[ar][ac]     = ra0;
        *(uint4*)&As[ar][ac + 8] = ra1;
        *(uint4*)&Bs[br][bc]     = rb0;
        *(uint4*)&Bs[br][bc + 8] = rb1;
        __syncthreads();
        if (kt + 1 < GK / 32) {
            int k0 = (kt + 1) * 32;
            const uint4* pa = (const uint4*)(A + (long)(m0 + ar) * GK + k0 + ac);
            const uint4* pb = (const uint4*)(Bp + (long)(k0 + br) * GN + n0 + bc);
            ra0 = pa[0]; ra1 = pa[1];
            rb0 = pb[0]; rb1 = pb[1];
        }
#pragma unroll
        for (int ks = 0; ks < 2; ks++) {
            uint32_t af[2][4], bf[4][4];
#pragma unroll
            for (int tm = 0; tm < 2; tm++)
                ldsm4(af[tm], aAddr0 + (tm * 16 * 40 + ks * 16) * 2);
#pragma unroll
            for (int p = 0; p < 4; p++)
                ldsm4t(bf[p], bAddr0 + (ks * 16 * 136 + p * 16) * 2);
#pragma unroll
            for (int tn = 0; tn < 8; tn++) {
                mma_bf16(acc[0][tn], af[0], &bf[tn >> 1][(tn & 1) * 2]);
                mma_bf16(acc[1][tn], af[1], &bf[tn >> 1][(tn & 1) * 2]);
            }
        }
        __syncthreads();
    }
#pragma unroll
    for (int tm = 0; tm < 2; tm++) {
#pragma unroll
        for (int tn = 0; tn < 8; tn++) {
            int m = m0 + wm + tm * 16 + lg;
            int n = n0 + wn + tn * 8 + 2 * lk;
            long i0 = (long)m * GN + n;
            long i1 = (long)(m + 8) * GN + n;
            float2 e0 = *(const float2*)&Etab[i0];
            float2 e1 = *(const float2*)&Etab[i1];
            *(__nv_bfloat162*)(Cp + i0) =
                __floats2bfloat162_rn(acc[tm][tn][0] + e0.x, acc[tm][tn][1] + e0.y);
            *(__nv_bfloat162*)(Cp + i1) =
                __floats2bfloat162_rn(acc[tm][tn][2] + e1.x, acc[tm][tn][3] + e1.y);
        }
    }
}

// ---------------- K1: gate finalize + out_{t-1} + attention score partials ----------
__global__ __launch_bounds__(256) void score_kernel(
    int t, int nch,
    const float* __restrict__ count,
    const float* __restrict__ attn_v, const float* __restrict__ attn_vb,
    const float* __restrict__ cov_w, const float* __restrict__ cov_b,
    const float* __restrict__ out_w, const float* __restrict__ out_b,
    float* __restrict__ d_out) {
    const int b = blockIdx.y, cx = blockIdx.x, tid = threadIdx.x;
    float hn = 0.f;
    if (t > 0) {
        const float* gi = g_gi + b * NGI;
        float gr = gi[tid], gz = gi[256 + tid], gin = gi[512 + tid], ghn = gi[768 + tid];
        float hold = g_h[((t - 1) & 1) * BB * HH + b * HH + tid];
        float r = 1.f / (1.f + expf(-gr));
        float z = 1.f / (1.f + expf(-gz));
        float n = tanhf(gin + r * ghn);
        hn = (1.f - z) * n + z * hold;
    }

    if (cx == nch) {  // aux block: h_t, xcat h-part, out_{t-1}
        __shared__ float s_x2[640];
        g_h[(t & 1) * BB * HH + b * HH + tid] = hn;
        if (t < TT) g_xcat[b * XW + 256 + tid] = hn;
        if (t > 0) {
            s_x2[tid] = hn;
            s_x2[256 + tid] = g_context[b * HH + tid];
            if (tid < CC) s_x2[512 + tid] = count[b * CC + tid];
            __syncthreads();
            const int warp = tid >> 5, lane = tid & 31;
            float* op = d_out + ((long)b * TT + (t - 1)) * CC;
#pragma unroll
            for (int i = 0; i < 14; i++) {
                int c = warp * 14 + i;
                if (c < CC) {
                    const float* wrow = out_w + (long)c * KX;
                    float acc = 0.f;
                    for (int k = lane; k < KX; k += 32)
                        acc = fmaf(wrow[k], s_x2[k], acc);
#pragma unroll
                    for (int o = 16; o > 0; o >>= 1)
                        acc += __shfl_xor_sync(0xffffffffu, acc, o);
                    if (lane == 0) op[c] = acc + out_b[c];
                }
            }
        }
        return;
    }

    const int lchunk = cx & 1, hq = cx >> 1, hh0 = hq * 64;
    __shared__ float s_hfull[HH];
    __shared__ float s_base[64], s_cw[64], s_v[64];
    s_hfull[tid] = hn;
    __syncthreads();
    if (tid < 64) {
        int h = hh0 + tid;
        s_base[tid] = cov_b[h] + s_hfull[h];
        s_cw[tid] = cov_w[h];
        s_v[tid] = attn_v[h];
    }
    __syncthreads();

    const int p = lchunk * 256 + tid;
    const float2 cov = *(const float2*)&g_cov[b * LL + 2 * p];
    const __nv_bfloat162* wf2 =
        (const __nv_bfloat162*)(g_Fh + ((long)b * H2 + 256 + hh0) * LL) + p;
    float a0 = (hq == 0) ? attn_vb[0] : 0.f, a1 = 0.f;
    float b0 = 0.f, b1 = 0.f;
#pragma unroll 8
    for (int hh = 0; hh < 64; hh += 2) {
        float2 w0 = __bfloat1622float2(wf2[(long)hh * 512]);
        float2 w1 = __bfloat1622float2(wf2[(long)(hh + 1) * 512]);
        float ba0 = s_base[hh], cw0 = s_cw[hh], vv0 = s_v[hh];
        float ba1 = s_base[hh + 1], cw1 = s_cw[hh + 1], vv1 = s_v[hh + 1];
        a0 = fmaf(vv0, ftanh(fmaf(cov.x, cw0, w0.x + ba0)), a0);
        a1 = fmaf(vv0, ftanh(fmaf(cov.y, cw0, w0.y + ba0)), a1);
        b0 = fmaf(vv1, ftanh(fmaf(cov.x, cw1, w1.x + ba1)), b0);
        b1 = fmaf(vv1, ftanh(fmaf(cov.y, cw1, w1.y + ba1)), b1);
    }
    *(float2*)&g_scores[hq * BB * LL + b * LL + 2 * p] = make_float2(a0 + b0, a1 + b1);
}

// ---------------- K2: softmax + coverage + context + xcat ctx-part + gi init ------
__global__ __launch_bounds__(256) void ctx_kernel(int t, const int* __restrict__ target) {
    const int b = blockIdx.y, c = blockIdx.x, tid = threadIdx.x;
    const int warp = tid >> 5, lane = tid & 31;
    __shared__ float s_alpha[LL];
    __shared__ float s_red[8];

    float4 p0 = ((const float4*)(g_scores + b * LL))[tid];
    float4 p1 = ((const float4*)(g_scores + 1 * BB * LL + b * LL))[tid];
    float4 p2 = ((const float4*)(g_scores + 2 * BB * LL + b * LL))[tid];
    float4 p3 = ((const float4*)(g_scores + 3 * BB * LL + b * LL))[tid];
    float4 sc = make_float4((p0.x + p1.x) + (p2.x + p3.x),
                            (p0.y + p1.y) + (p2.y + p3.y),
                            (p0.z + p1.z) + (p2.z + p3.z),
                            (p0.w + p1.w) + (p2.w + p3.w));
    float mx = fmaxf(fmaxf(sc.x, sc.y), fmaxf(sc.z, sc.w));
#pragma unroll
    for (int o = 16; o > 0; o >>= 1) mx = fmaxf(mx, __shfl_xor_sync(0xffffffffu, mx, o));
    if (lane == 0) s_red[warp] = mx;
    __syncthreads();
    float M = s_red[0];
#pragma unroll
    for (int w = 1; w < 8; w++) M = fmaxf(M, s_red[w]);
    float e0 = __expf(sc.x - M), e1 = __expf(sc.y - M);
    float e2 = __expf(sc.z - M), e3 = __expf(sc.w - M);
    float sm = e0 + e1 + e2 + e3;
#pragma unroll
    for (int o = 16; o > 0; o >>= 1) sm += __shfl_xor_sync(0xffffffffu, sm, o);
    __syncthreads();
    if (lane == 0) s_red[warp] = sm;
    __syncthreads();
    float S = 0.f;
#pragma unroll
    for (int w = 0; w < 8; w++) S += s_red[w];
    float inv = 1.f / S;
    float4 al = make_float4(e0 * inv, e1 * inv, e2 * inv, e3 * inv);
    ((float4*)s_alpha)[tid] = al;
    if (c == 0) {
        float4 cv = ((float4*)(g_cov + b * LL))[tid];
        cv.x += al.x; cv.y += al.y; cv.z += al.z; cv.w += al.w;
        ((float4*)(g_cov + b * LL))[tid] = cv;
    }
    __syncthreads();

    const __nv_bfloat16* fb = g_Fh + (long)b * H2 * LL;
#pragma unroll
    for (int r = 0; r < 4; r++) {
        int d = c * 32 + warp * 4 + r;
        const uint4* row = (const uint4*)(fb + (long)d * LL);
        float sum = 0.f;
#pragma unroll
        for (int it = 0; it < 4; it++) {
            uint4 f8 = row[it * 32 + lane];
            const float4* ap = (const float4*)&s_alpha[(it * 32 + lane) * 8];
            float4 a0 = ap[0], a1 = ap[1];
            float2 f0 = __bfloat1622float2(*(__nv_bfloat162*)&f8.x);
            float2 f1 = __bfloat1622float2(*(__nv_bfloat162*)&f8.y);
            float2 f2 = __bfloat1622float2(*(__nv_bfloat162*)&f8.z);
            float2 f3 = __bfloat1622float2(*(__nv_bfloat162*)&f8.w);
            sum = fmaf(f0.x, a0.x, sum); sum = fmaf(f0.y, a0.y, sum);
            sum = fmaf(f1.x, a0.z, sum); sum = fmaf(f1.y, a0.w, sum);
            sum = fmaf(f2.x, a1.x, sum); sum = fmaf(f2.y, a1.y, sum);
            sum = fmaf(f3.x, a1.z, sum); sum = fmaf(f3.y, a1.w, sum);
        }
#pragma unroll
        for (int o = 16; o > 0; o >>= 1) sum += __shfl_xor_sync(0xffffffffu, sum, o);
        if (lane == 0) {
            g_context[b * HH + d] = sum;
            g_xcat[b * XW + d] = sum;
        }
    }

    if (tid < 128) {
        int y = (t == 0) ? 1 : target[b * TT + (t - 1)];
        int j = c * 128 + tid;
        g_gi[b * NGI + j] = g_gemb[(long)y * NGI + j] + g_gcntb[(long)b * NGI + j];
    }
}

// ---------------- K3: GRU gate GEMM, K=512 ([ctx|h]), K-split atomic ----------------
__global__ __launch_bounds__(256) void gru_gemm_kernel() {
    const int nt = blockIdx.x & 15, ks = blockIdx.x >> 4;
    const int n0 = nt * 64, k0 = ks * 64;
    const int tid = threadIdx.x;
    __shared__ float Xs[16][68];
    __shared__ float Ws[16][64];
    const int ml = tid >> 2, kq = (tid & 3) * 4;
    const int kw = tid >> 4, nn = (tid & 15) * 4;
    const int ty = tid >> 4, tx = tid & 15;
    float acc[4][4];
#pragma unroll
    for (int i = 0; i < 4; i++)
#pragma unroll
        for (int j = 0; j < 4; j++) acc[i][j] = 0.f;

#pragma unroll
    for (int kt = 0; kt < 4; kt++) {
        const int k = k0 + kt * 16;
        float4 x4 = *(const float4*)&g_xcat[ml * XW + k + kq];
        Xs[kq + 0][ml] = x4.x; Xs[kq + 1][ml] = x4.y;
        Xs[kq + 2][ml] = x4.z; Xs[kq + 3][ml] = x4.w;
        const int row = (k < 256) ? (256 + k + kw) : (623 + (k - 256) + kw);
        *(float4*)&Ws[kw][nn] = *(const float4*)&g_WcatT[(long)row * NGI + n0 + nn];
        __syncthreads();
#pragma unroll
        for (int kk = 0; kk < 16; kk++) {
            float rx[4], rw[4];
#pragma unroll
            for (int i = 0; i < 4; i++) rx[i] = Xs[kk][ty * 4 + i];
#pragma unroll
            for (int j = 0; j < 4; j++) rw[j] = Ws[kk][tx * 4 + j];
#pragma unroll
            for (int i = 0; i < 4; i++)
#pragma unroll
                for (int j = 0; j < 4; j++) acc[i][j] = fmaf(rx[i], rw[j], acc[i][j]);
        }
        __syncthreads();
    }
#pragma unroll
    for (int i = 0; i < 4; i++)
#pragma unroll
        for (int j = 0; j < 4; j++)
            atomicAdd(&g_gi[(ty * 4 + i) * NGI + n0 + tx * 4 + j], acc[i][j]);
}

// ---------------- launch ----------------
extern "C" void kernel_launch(void* const* d_in, const int* in_sizes, int n_in,
                              void* d_out, int out_size) {
    const float* fm      = (const float*)d_in[0];
    const float* count   = (const float*)d_in[1];
    const int*   target  = (const int*)d_in[2];
    const float* conv_w  = (const float*)d_in[3];
    const float* conv_b  = (const float*)d_in[4];
    const float* emb     = (const float*)d_in[5];
    const float* gru_wih = (const float*)d_in[6];
    const float* gru_whh = (const float*)d_in[7];
    const float* gru_bih = (const float*)d_in[8];
    const float* gru_bhh = (const float*)d_in[9];
    const float* attn_w  = (const float*)d_in[10];
    const float* attn_b  = (const float*)d_in[11];
    const float* attn_v  = (const float*)d_in[12];
    const float* attn_vb = (const float*)d_in[13];
    const float* cov_w   = (const float*)d_in[14];
    const float* cov_b   = (const float*)d_in[15];
    const float* out_w   = (const float*)d_in[16];
    const float* out_b   = (const float*)d_in[17];
    float* out = (float*)d_out;

    float *pW2, *pPeB, *pE;
    __nv_bfloat16 *pFh, *pFmh, *pW2h;
    cudaGetSymbolAddress((void**)&pFh, g_Fh);
    cudaGetSymbolAddress((void**)&pW2, g_W2);
    cudaGetSymbolAddress((void**)&pPeB, g_peB);
    cudaGetSymbolAddress((void**)&pE, g_E);
    cudaGetSymbolAddress((void**)&pFmh, g_fmh);
    cudaGetSymbolAddress((void**)&pW2h, g_W2h);

    // once-only side streams + events (capture DAG rooted in s0 = default stream)
    static cudaStream_t s1 = nullptr, s2 = nullptr;
    static cudaEvent_t evPrep = nullptr, evMain = nullptr, evSide = nullptr;
    if (!s1) {
        cudaStreamCreateWithFlags(&s1, cudaStreamNonBlocking);
        cudaStreamCreateWithFlags(&s2, cudaStreamNonBlocking);
        cudaEventCreateWithFlags(&evPrep, cudaEventDisableTiming);
        cudaEventCreateWithFlags(&evMain, cudaEventDisableTiming);
        cudaEventCreateWithFlags(&evSide, cudaEventDisableTiming);
    }
    cudaStream_t s0 = (cudaStream_t)0;

    // s0 (capture origin): prep, then fork
    prep_kernel<<<1024, 256, 0, s0>>>(gru_wih, gru_whh, gru_bih, gru_bhh, conv_w, conv_b);
    cudaEventRecord(evPrep, s0);

    // s1: small GEMMs + W2 convert (forked from s0)
    cudaStreamWaitEvent(s1, evPrep, 0);
    sgemm64_kernel<<<dim3(16, 4), 256, 0, s1>>>(attn_w, conv_w, pW2 + 256 * CIN,
                                                256, CIN, H2, nullptr);
    sgemm64_kernel<<<dim3(16, 4), 256, 0, s1>>>(attn_w, pPeB, pE + 256 * LL,
                                                256, LL, H2, attn_b);
    cvt_w2_kernel<<<256, 256, 0, s1>>>();
    cudaEventRecord(evMain, s1);

    // s2: gate-precompute (forked from s0)
    cudaStreamWaitEvent(s2, evPrep, 0);
    gemb_kernel<<<CC, 256, 0, s2>>>(emb);
    gcnt_kernel<<<BB, 256, 0, s2>>>(count);
    cudaEventRecord(evSide, s2);

    // s0: fm bf16 convert overlaps s1/s2 work, then join and run main GEMM
    cvt_fm_kernel<<<2048, 256, 0, s0>>>(fm);
    cudaStreamWaitEvent(s0, evMain, 0);
    mma_gemm_kernel<<<dim3(8, 4, BB), 256, 0, s0>>>(pW2h, pFmh, pFh, pE);
    cudaStreamWaitEvent(s0, evSide, 0);

    for (int t = 0; t < TT; t++) {
        score_kernel<<<dim3(9, BB), 256>>>(t, 8, count, attn_v, attn_vb,
                                           cov_w, cov_b, out_w, out_b, out);
        ctx_kernel<<<dim3(8, BB), 256>>>(t, target);
        gru_gemm_kernel<<<128, 256>>>();
    }
    score_kernel<<<dim3(1, BB), 256>>>(TT, 0, count, attn_v, attn_vb,
                                       cov_w, cov_b, out_w, out_b, out);
}

// round 15
// speedup vs baseline: 1.1790x; 1.0577x over previous
#include <cuda_runtime.h>
#include <cuda_bf16.h>
#include <math.h>
#include <stdint.h>
#include <string.h>

// ---------------- problem constants ----------------
#define BB   64
#define LL   1024
#define HH   256
#define H2   512
#define CC   111
#define TT   64
#define CIN  1024
#define DD   256
#define KCAT 879
#define NGI  1024
#define KX   623
#define XW   512        // xcat: [ctx(256) | h(256)]
#define GM   512
#define GN   1024
#define GK   1024

// ---------------- device scratch ----------------
__device__ __nv_bfloat16 g_Fh[(long)BB * H2 * LL];  // rows 0-255: ctx feats, 256-511: Wf
__device__ float g_scores[4 * BB * LL];
__device__ float g_cov[BB * LL];
__device__ float g_h[2 * BB * HH];
__device__ float g_context[BB * HH];
__device__ float g_gi[BB * NGI];
__device__ float g_xcat[BB * XW];
__device__ float g_WcatT[KCAT * NGI];   // rows: emb 0-255, ctx 256-511, cnt 512-622, h 623-878
__device__ float g_gbias[NGI];
__device__ float g_gemb[CC * NGI];
__device__ float g_gcntb[BB * NGI];
__device__ float g_W2[H2 * CIN];
__device__ float g_peB[H2 * LL];
__device__ float g_E[H2 * LL];
__device__ __nv_bfloat16 g_fmh[(long)BB * CIN * LL];
__device__ __nv_bfloat16 g_W2h[H2 * CIN];

__device__ __forceinline__ float ftanh(float x) {
    float y; asm("tanh.approx.f32 %0, %1;" : "=f"(y) : "f"(x)); return y;
}
__device__ __forceinline__ float pe_val(int l, int o) {
    float f = expf((float)(o & ~1) * (-9.210340371976184f / 512.f));
    float a = (float)l * f;
    return (o & 1) ? cosf(a) : sinf(a);
}
__device__ __forceinline__ uint32_t s2u(const void* p) {
    return (uint32_t)__cvta_generic_to_shared(p);
}
__device__ __forceinline__ void gdc_wait() {
    asm volatile("griddepcontrol.wait;" ::: "memory");
}
__device__ __forceinline__ void ldsm4(uint32_t* r, uint32_t a) {
    asm volatile("ldmatrix.sync.aligned.m8n8.x4.shared.b16 {%0,%1,%2,%3}, [%4];"
                 : "=r"(r[0]), "=r"(r[1]), "=r"(r[2]), "=r"(r[3]) : "r"(a));
}
__device__ __forceinline__ void ldsm4t(uint32_t* r, uint32_t a) {
    asm volatile("ldmatrix.sync.aligned.m8n8.x4.trans.shared.b16 {%0,%1,%2,%3}, [%4];"
                 : "=r"(r[0]), "=r"(r[1]), "=r"(r[2]), "=r"(r[3]) : "r"(a));
}
__device__ __forceinline__ void mma_bf16(float* d, const uint32_t* a, const uint32_t* b) {
    asm volatile(
        "mma.sync.aligned.m16n8k16.row.col.f32.bf16.bf16.f32 "
        "{%0,%1,%2,%3}, {%4,%5,%6,%7}, {%8,%9}, {%0,%1,%2,%3};\n"
        : "+f"(d[0]), "+f"(d[1]), "+f"(d[2]), "+f"(d[3])
        : "r"(a[0]), "r"(a[1]), "r"(a[2]), "r"(a[3]), "r"(b[0]), "r"(b[1]));
}

// ---------------- prep ----------------
__global__ void prep_kernel(const float* __restrict__ wih, const float* __restrict__ whh,
                            const float* __restrict__ bih, const float* __restrict__ bhh,
                            const float* __restrict__ convw, const float* __restrict__ convb) {
    const long R1 = (long)KCAT * NGI;
    const long R2 = R1 + NGI;
    const long R3 = R2 + 256L * CIN;
    const long R4 = R3 + (long)H2 * LL;
    const long R5 = R4 + 256L * LL;
    const long ZTOT = 2L*BB*HH + BB*LL + BB*HH + BB*XW;
    const long TOTAL = R5 + ZTOT;
    for (long idx = (long)blockIdx.x * blockDim.x + threadIdx.x; idx < TOTAL;
         idx += (long)gridDim.x * blockDim.x) {
        long i = idx;
        if (i < R1) {
            int k = (int)(i >> 10), j = (int)(i & 1023);
            float v = 0.f;
            if (j < 768) {
                if (k < KX) v = wih[j * KX + k];
                else if (j < 512) v = whh[j * HH + (k - KX)];
            } else {
                if (k >= KX) v = whh[(j - 768 + 512) * HH + (k - KX)];
            }
            g_WcatT[i] = v; continue;
        }
        if (i < R2) { int j = (int)(i - R1);
            g_gbias[j] = (j < 512) ? bih[j] + bhh[j] : (j < 768) ? bih[j] : bhh[j - 256];
            continue; }
        if (i < R3) { long p = i - R2; g_W2[p] = convw[p]; continue; }
        if (i < R4) { long p = i - R3; int o = (int)(p >> 10), l = (int)(p & 1023);
            g_peB[p] = pe_val(l, o) + convb[o]; continue; }
        if (i < R5) { long p = i - R4; int m = (int)(p >> 10), l = (int)(p & 1023);
            g_E[p] = convb[m] + pe_val(l, m); continue; }
        long p = i - R5;
        if (p < 2L*BB*HH) { g_h[p] = 0.f; continue; } p -= 2L*BB*HH;
        if (p < BB*LL) { g_cov[p] = 0.f; continue; } p -= BB*LL;
        if (p < BB*HH) { g_context[p] = 0.f; continue; } p -= BB*HH;
        g_xcat[p] = 0.f;
    }
}

// ---------------- precompute gemb[c] = emb[c] @ Wemb ----------------
__global__ __launch_bounds__(256) void gemb_kernel(const float* __restrict__ emb) {
    const int c = blockIdx.x, tid = threadIdx.x;
    __shared__ float s_e[DD];
    s_e[tid] = emb[c * DD + tid];
    __syncthreads();
    const int j0 = tid * 4;
    float4 acc = make_float4(0.f, 0.f, 0.f, 0.f);
#pragma unroll 8
    for (int k = 0; k < DD; k++) {
        float4 w = *(const float4*)&g_WcatT[(long)k * NGI + j0];
        float e = s_e[k];
        acc.x = fmaf(e, w.x, acc.x); acc.y = fmaf(e, w.y, acc.y);
        acc.z = fmaf(e, w.z, acc.z); acc.w = fmaf(e, w.w, acc.w);
    }
    *(float4*)&g_gemb[(long)c * NGI + j0] = acc;
}

// ---------------- precompute gcntb[b] = gbias + count[b] @ Wcnt ----------------
__global__ __launch_bounds__(256) void gcnt_kernel(const float* __restrict__ count) {
    const int b = blockIdx.x, tid = threadIdx.x;
    __shared__ float s_c[CC];
    if (tid < CC) s_c[tid] = count[b * CC + tid];
    __syncthreads();
    const int j0 = tid * 4;
    float4 acc = *(const float4*)&g_gbias[j0];
#pragma unroll 8
    for (int k = 0; k < CC; k++) {
        float4 w = *(const float4*)&g_WcatT[(long)(512 + k) * NGI + j0];
        float e = s_c[k];
        acc.x = fmaf(e, w.x, acc.x); acc.y = fmaf(e, w.y, acc.y);
        acc.z = fmaf(e, w.z, acc.z); acc.w = fmaf(e, w.w, acc.w);
    }
    *(float4*)&g_gcntb[(long)b * NGI + j0] = acc;
}

// ---------------- 64x64-tile SGEMM (small prep GEMMs, wide grid) ----------------
__global__ __launch_bounds__(256) void sgemm64_kernel(
    const float* __restrict__ A, const float* __restrict__ B, float* __restrict__ C,
    int M, int N, int K, const float* __restrict__ bias) {
    const int tid = threadIdx.x;
    const int n0 = blockIdx.x * 64, m0 = blockIdx.y * 64;
    __shared__ float As[16][64];
    __shared__ float Bs[16][68];
    const int ty = tid >> 4, tx = tid & 15;
    const int arow = tid >> 2, acol = (tid & 3) * 4;
    const int brow = tid >> 4, bcol = (tid & 15) * 4;
    float acc[4][4];
#pragma unroll
    for (int i = 0; i < 4; i++)
#pragma unroll
        for (int j = 0; j < 4; j++) acc[i][j] = 0.f;

    for (int k0 = 0; k0 < K; k0 += 16) {
        float4 a4 = *(const float4*)&A[(long)(m0 + arow) * K + k0 + acol];
        As[acol + 0][arow] = a4.x; As[acol + 1][arow] = a4.y;
        As[acol + 2][arow] = a4.z; As[acol + 3][arow] = a4.w;
        *(float4*)&Bs[brow][bcol] = *(const float4*)&B[(long)(k0 + brow) * N + n0 + bcol];
        __syncthreads();
#pragma unroll
        for (int kk = 0; kk < 16; kk++) {
            float ra[4], rb[4];
#pragma unroll
            for (int i = 0; i < 4; i++) ra[i] = As[kk][ty * 4 + i];
#pragma unroll
            for (int j = 0; j < 4; j++) rb[j] = Bs[kk][tx * 4 + j];
#pragma unroll
            for (int i = 0; i < 4; i++)
#pragma unroll
                for (int j = 0; j < 4; j++) acc[i][j] = fmaf(ra[i], rb[j], acc[i][j]);
        }
        __syncthreads();
    }
#pragma unroll
    for (int i = 0; i < 4; i++) {
        int m = m0 + ty * 4 + i;
        float bia = bias ? bias[m] : 0.f;
#pragma unroll
        for (int j = 0; j < 4; j++)
            C[(long)m * N + n0 + tx * 4 + j] = acc[i][j] + bia;
    }
}

// ---------------- fp32 -> bf16: feature map only ----------------
__global__ void cvt_fm_kernel(const float* __restrict__ fm) {
    const long N1 = (long)BB * CIN * LL / 4;
    __nv_bfloat162* fo = (__nv_bfloat162*)g_fmh;
    for (long i = (long)blockIdx.x * blockDim.x + threadIdx.x; i < N1;
         i += (long)gridDim.x * blockDim.x) {
        float4 v = ((const float4*)fm)[i];
        fo[2 * i]     = __floats2bfloat162_rn(v.x, v.y);
        fo[2 * i + 1] = __floats2bfloat162_rn(v.z, v.w);
    }
}

// ---------------- fp32 -> bf16: W2 ----------------
__global__ void cvt_w2_kernel() {
    const long N2 = (long)H2 * CIN / 4;
    __nv_bfloat162* wo = (__nv_bfloat162*)g_W2h;
    for (long j = (long)blockIdx.x * blockDim.x + threadIdx.x; j < N2;
         j += (long)gridDim.x * blockDim.x) {
        float4 v = ((const float4*)g_W2)[j];
        wo[2 * j]     = __floats2bfloat162_rn(v.x, v.y);
        wo[2 * j + 1] = __floats2bfloat162_rn(v.z, v.w);
    }
}

// ---------------- bf16 tensor-core main GEMM, bf16 output ----------------
__global__ __launch_bounds__(256, 2) void mma_gemm_kernel(
    const __nv_bfloat16* __restrict__ A, const __nv_bfloat16* __restrict__ Bg,
    __nv_bfloat16* __restrict__ Cg, const float* __restrict__ Etab) {
    const int tid = threadIdx.x;
    const int bx = blockIdx.x, by = blockIdx.y, b = blockIdx.z;
    const __nv_bfloat16* Bp = Bg + (long)b * GK * GN;
    __nv_bfloat16* Cp = Cg + (long)b * GM * GN;
    __shared__ __nv_bfloat16 As[128][40];
    __shared__ __nv_bfloat16 Bs[32][136];
    const int w = tid >> 5, lane = tid & 31;
    const int wm = (w & 3) * 32, wn = (w >> 2) * 64;
    const int m0 = by * 128, n0 = bx * 128;
    const int lg = lane >> 2, lk = lane & 3;

    float acc[2][8][4];
#pragma unroll
    for (int i = 0; i < 2; i++)
#pragma unroll
        for (int j = 0; j < 8; j++)
#pragma unroll
            for (int c = 0; c < 4; c++) acc[i][j][c] = 0.f;

    const int ar = tid >> 1, ac = (tid & 1) * 16;
    const int br = tid >> 3, bc = (tid & 7) * 16;
    const uint32_t aAddr0 = s2u(&As[wm + (lane & 15)][(lane >> 4) * 8]);
    const uint32_t bAddr0 = s2u(&Bs[lane & 15][wn + (lane >> 4) * 8]);

    uint4 ra0, ra1, rb0, rb1;
    {
        const uint4* pa = (const uint4*)(A + (long)(m0 + ar) * GK + ac);
        const uint4* pb = (const uint4*)(Bp + (long)br * GN + n0 + bc);
        ra0 = pa[0]; ra1 = pa[1];
        rb0 = pb[0]; rb1 = pb[1];
    }

    for (int kt = 0; kt < GK / 32; kt++) {
        *(uint4*)&As[ar][ac]     = ra0;
        *(uint4*)&As[ar][ac + 8] = ra1;
        *(uint4*)&Bs[br][bc]     = rb0;
        *(uint4*)&Bs[br][bc + 8] = rb1;
        __syncthreads();
        if (kt + 1 < GK / 32) {
            int k0 = (kt + 1) * 32;
            const uint4* pa = (const uint4*)(A + (long)(m0 + ar) * GK + k0 + ac);
            const uint4* pb = (const uint4*)(Bp + (long)(k0 + br) * GN + n0 + bc);
            ra0 = pa[0]; ra1 = pa[1];
            rb0 = pb[0]; rb1 = pb[1];
        }
#pragma unroll
        for (int ks = 0; ks < 2; ks++) {
            uint32_t af[2][4], bf[4][4];
#pragma unroll
            for (int tm = 0; tm < 2; tm++)
                ldsm4(af[tm], aAddr0 + (tm * 16 * 40 + ks * 16) * 2);
#pragma unroll
            for (int p = 0; p < 4; p++)
                ldsm4t(bf[p], bAddr0 + (ks * 16 * 136 + p * 16) * 2);
#pragma unroll
            for (int tn = 0; tn < 8; tn++) {
                mma_bf16(acc[0][tn], af[0], &bf[tn >> 1][(tn & 1) * 2]);
                mma_bf16(acc[1][tn], af[1], &bf[tn >> 1][(tn & 1) * 2]);
            }
        }
        __syncthreads();
    }
#pragma unroll
    for (int tm = 0; tm < 2; tm++) {
#pragma unroll
        for (int tn = 0; tn < 8; tn++) {
            int m = m0 + wm + tm * 16 + lg;
            int n = n0 + wn + tn * 8 + 2 * lk;
            long i0 = (long)m * GN + n;
            long i1 = (long)(m + 8) * GN + n;
            float2 e0 = *(const float2*)&Etab[i0];
            float2 e1 = *(const float2*)&Etab[i1];
            *(__nv_bfloat162*)(Cp + i0) =
                __floats2bfloat162_rn(acc[tm][tn][0] + e0.x, acc[tm][tn][1] + e0.y);
            *(__nv_bfloat162*)(Cp + i1) =
                __floats2bfloat162_rn(acc[tm][tn][2] + e1.x, acc[tm][tn][3] + e1.y);
        }
    }
}

// ---------------- K1: gate finalize + out_{t-1} + attention score partials ----------
// PDL: prefetch param vectors pre-wait; all predecessor data read post-wait.
__global__ __launch_bounds__(256) void score_kernel(
    int t, int nch,
    const float* __restrict__ count,
    const float* __restrict__ attn_v, const float* __restrict__ attn_vb,
    const float* __restrict__ cov_w, const float* __restrict__ cov_b,
    const float* __restrict__ out_w, const float* __restrict__ out_b,
    float* __restrict__ d_out) {
    const int b = blockIdx.y, cx = blockIdx.x, tid = threadIdx.x;
    const int lchunk = cx & 1, hq = cx >> 1, hh0 = hq * 64;
    __shared__ float s_hfull[HH];
    __shared__ float s_base[64], s_cw[64], s_v[64], s_cb[64];

    // pre-wait prologue: param-only loads (no dependence on prior kernel)
    if (cx != nch && tid < 64) {
        int h = hh0 + tid;
        s_cb[tid] = cov_b[h];
        s_cw[tid] = cov_w[h];
        s_v[tid]  = attn_v[h];
    }
    gdc_wait();

    float hn = 0.f;
    if (t > 0) {
        const float* gi = g_gi + b * NGI;
        float gr = gi[tid], gz = gi[256 + tid], gin = gi[512 + tid], ghn = gi[768 + tid];
        float hold = g_h[((t - 1) & 1) * BB * HH + b * HH + tid];
        float r = 1.f / (1.f + expf(-gr));
        float z = 1.f / (1.f + expf(-gz));
        float n = tanhf(gin + r * ghn);
        hn = (1.f - z) * n + z * hold;
    }

    if (cx == nch) {  // aux block: h_t, xcat h-part, out_{t-1}
        __shared__ float s_x2[640];
        g_h[(t & 1) * BB * HH + b * HH + tid] = hn;
        if (t < TT) g_xcat[b * XW + 256 + tid] = hn;
        if (t > 0) {
            s_x2[tid] = hn;
            s_x2[256 + tid] = g_context[b * HH + tid];
            if (tid < CC) s_x2[512 + tid] = count[b * CC + tid];
            __syncthreads();
            const int warp = tid >> 5, lane = tid & 31;
            float* op = d_out + ((long)b * TT + (t - 1)) * CC;
#pragma unroll
            for (int i = 0; i < 14; i++) {
                int c = warp * 14 + i;
                if (c < CC) {
                    const float* wrow = out_w + (long)c * KX;
                    float acc = 0.f;
                    for (int k = lane; k < KX; k += 32)
                        acc = fmaf(wrow[k], s_x2[k], acc);
#pragma unroll
                    for (int o = 16; o > 0; o >>= 1)
                        acc += __shfl_xor_sync(0xffffffffu, acc, o);
                    if (lane == 0) op[c] = acc + out_b[c];
                }
            }
        }
        return;
    }

    s_hfull[tid] = hn;
    __syncthreads();
    if (tid < 64) s_base[tid] = s_cb[tid] + s_hfull[hh0 + tid];
    __syncthreads();

    const int p = lchunk * 256 + tid;
    const float2 cov = *(const float2*)&g_cov[b * LL + 2 * p];
    const __nv_bfloat162* wf2 =
        (const __nv_bfloat162*)(g_Fh + ((long)b * H2 + 256 + hh0) * LL) + p;
    float a0 = (hq == 0) ? attn_vb[0] : 0.f, a1 = 0.f;
    float b0 = 0.f, b1 = 0.f;
#pragma unroll 8
    for (int hh = 0; hh < 64; hh += 2) {
        float2 w0 = __bfloat1622float2(wf2[(long)hh * 512]);
        float2 w1 = __bfloat1622float2(wf2[(long)(hh + 1) * 512]);
        float ba0 = s_base[hh], cw0 = s_cw[hh], vv0 = s_v[hh];
        float ba1 = s_base[hh + 1], cw1 = s_cw[hh + 1], vv1 = s_v[hh + 1];
        a0 = fmaf(vv0, ftanh(fmaf(cov.x, cw0, w0.x + ba0)), a0);
        a1 = fmaf(vv0, ftanh(fmaf(cov.y, cw0, w0.y + ba0)), a1);
        b0 = fmaf(vv1, ftanh(fmaf(cov.x, cw1, w1.x + ba1)), b0);
        b1 = fmaf(vv1, ftanh(fmaf(cov.y, cw1, w1.y + ba1)), b1);
    }
    *(float2*)&g_scores[hq * BB * LL + b * LL + 2 * p] = make_float2(a0 + b0, a1 + b1);
}

// ---------------- K2: softmax + coverage + context + xcat ctx-part + gi init ------
__global__ __launch_bounds__(256) void ctx_kernel(int t, const int* __restrict__ target) {
    const int b = blockIdx.y, c = blockIdx.x, tid = threadIdx.x;
    const int warp = tid >> 5, lane = tid & 31;
    __shared__ float s_alpha[LL];
    __shared__ float s_red[8];

    gdc_wait();

    float4 p0 = ((const float4*)(g_scores + b * LL))[tid];
    float4 p1 = ((const float4*)(g_scores + 1 * BB * LL + b * LL))[tid];
    float4 p2 = ((const float4*)(g_scores + 2 * BB * LL + b * LL))[tid];
    float4 p3 = ((const float4*)(g_scores + 3 * BB * LL + b * LL))[tid];
    float4 sc = make_float4((p0.x + p1.x) + (p2.x + p3.x),
                            (p0.y + p1.y) + (p2.y + p3.y),
                            (p0.z + p1.z) + (p2.z + p3.z),
                            (p0.w + p1.w) + (p2.w + p3.w));
    float mx = fmaxf(fmaxf(sc.x, sc.y), fmaxf(sc.z, sc.w));
#pragma unroll
    for (int o = 16; o > 0; o >>= 1) mx = fmaxf(mx, __shfl_xor_sync(0xffffffffu, mx, o));
    if (lane == 0) s_red[warp] = mx;
    __syncthreads();
    float M = s_red[0];
#pragma unroll
    for (int w = 1; w < 8; w++) M = fmaxf(M, s_red[w]);
    float e0 = __expf(sc.x - M), e1 = __expf(sc.y - M);
    float e2 = __expf(sc.z - M), e3 = __expf(sc.w - M);
    float sm = e0 + e1 + e2 + e3;
#pragma unroll
    for (int o = 16; o > 0; o >>= 1) sm += __shfl_xor_sync(0xffffffffu, sm, o);
    __syncthreads();
    if (lane == 0) s_red[warp] = sm;
    __syncthreads();
    float S = 0.f;
#pragma unroll
    for (int w = 0; w < 8; w++) S += s_red[w];
    float inv = 1.f / S;
    float4 al = make_float4(e0 * inv, e1 * inv, e2 * inv, e3 * inv);
    ((float4*)s_alpha)[tid] = al;
    if (c == 0) {
        float4 cv = ((float4*)(g_cov + b * LL))[tid];
        cv.x += al.x; cv.y += al.y; cv.z += al.z; cv.w += al.w;
        ((float4*)(g_cov + b * LL))[tid] = cv;
    }
    __syncthreads();

    const __nv_bfloat16* fb = g_Fh + (long)b * H2 * LL;
#pragma unroll
    for (int r = 0; r < 4; r++) {
        int d = c * 32 + warp * 4 + r;
        const uint4* row = (const uint4*)(fb + (long)d * LL);
        float sum = 0.f;
#pragma unroll
        for (int it = 0; it < 4; it++) {
            uint4 f8 = row[it * 32 + lane];
            const float4* ap = (const float4*)&s_alpha[(it * 32 + lane) * 8];
            float4 a0 = ap[0], a1 = ap[1];
            float2 f0 = __bfloat1622float2(*(__nv_bfloat162*)&f8.x);
            float2 f1 = __bfloat1622float2(*(__nv_bfloat162*)&f8.y);
            float2 f2 = __bfloat1622float2(*(__nv_bfloat162*)&f8.z);
            float2 f3 = __bfloat1622float2(*(__nv_bfloat162*)&f8.w);
            sum = fmaf(f0.x, a0.x, sum); sum = fmaf(f0.y, a0.y, sum);
            sum = fmaf(f1.x, a0.z, sum); sum = fmaf(f1.y, a0.w, sum);
            sum = fmaf(f2.x, a1.x, sum); sum = fmaf(f2.y, a1.y, sum);
            sum = fmaf(f3.x, a1.z, sum); sum = fmaf(f3.y, a1.w, sum);
        }
#pragma unroll
        for (int o = 16; o > 0; o >>= 1) sum += __shfl_xor_sync(0xffffffffu, sum, o);
        if (lane == 0) {
            g_context[b * HH + d] = sum;
            g_xcat[b * XW + d] = sum;
        }
    }

    if (tid < 128) {
        int y = (t == 0) ? 1 : target[b * TT + (t - 1)];
        int j = c * 128 + tid;
        g_gi[b * NGI + j] = g_gemb[(long)y * NGI + j] + g_gcntb[(long)b * NGI + j];
    }
}

// ---------------- K3: GRU gate GEMM, K=512, K-split atomic ----------------
// PDL: preload ALL weight tiles pre-wait (weights never change during loop).
__global__ __launch_bounds__(256) void gru_gemm_kernel() {
    const int nt = blockIdx.x & 15, ks = blockIdx.x >> 4;
    const int n0 = nt * 64, k0 = ks * 64;
    const int tid = threadIdx.x;
    __shared__ float Ws[4][16][64];
    __shared__ float Xs[16][68];
    const int ml = tid >> 2, kq = (tid & 3) * 4;
    const int kw = tid >> 4, nn = (tid & 15) * 4;
    const int ty = tid >> 4, tx = tid & 15;

    // pre-wait: weight tiles (stable across the loop)
#pragma unroll
    for (int kt = 0; kt < 4; kt++) {
        const int k = k0 + kt * 16;
        const int row = (k < 256) ? (256 + k + kw) : (623 + (k - 256) + kw);
        *(float4*)&Ws[kt][kw][nn] = *(const float4*)&g_WcatT[(long)row * NGI + n0 + nn];
    }
    gdc_wait();

    float acc[4][4];
#pragma unroll
    for (int i = 0; i < 4; i++)
#pragma unroll
        for (int j = 0; j < 4; j++) acc[i][j] = 0.f;

#pragma unroll
    for (int kt = 0; kt < 4; kt++) {
        const int k = k0 + kt * 16;
        float4 x4 = *(const float4*)&g_xcat[ml * XW + k + kq];
        Xs[kq + 0][ml] = x4.x; Xs[kq + 1][ml] = x4.y;
        Xs[kq + 2][ml] = x4.z; Xs[kq + 3][ml] = x4.w;
        __syncthreads();
#pragma unroll
        for (int kk = 0; kk < 16; kk++) {
            float rx[4], rw[4];
#pragma unroll
            for (int i = 0; i < 4; i++) rx[i] = Xs[kk][ty * 4 + i];
#pragma unroll
            for (int j = 0; j < 4; j++) rw[j] = Ws[kt][kk][tx * 4 + j];
#pragma unroll
            for (int i = 0; i < 4; i++)
#pragma unroll
                for (int j = 0; j < 4; j++) acc[i][j] = fmaf(rx[i], rw[j], acc[i][j]);
        }
        __syncthreads();
    }
#pragma unroll
    for (int i = 0; i < 4; i++)
#pragma unroll
        for (int j = 0; j < 4; j++)
            atomicAdd(&g_gi[(ty * 4 + i) * NGI + n0 + tx * 4 + j], acc[i][j]);
}

// ---------------- PDL launch helper ----------------
template <typename... ExpArgs, typename... Args>
static inline void pdl(dim3 g, dim3 blk, void (*k)(ExpArgs...), Args&&... a) {
    cudaLaunchConfig_t cfg;
    memset(&cfg, 0, sizeof(cfg));
    cfg.gridDim = g; cfg.blockDim = blk; cfg.stream = (cudaStream_t)0;
    cudaLaunchAttribute at;
    at.id = cudaLaunchAttributeProgrammaticStreamSerialization;
    at.val.programmaticStreamSerializationAllowed = 1;
    cfg.attrs = &at; cfg.numAttrs = 1;
    cudaLaunchKernelEx(&cfg, k, static_cast<Args&&>(a)...);
}

// ---------------- launch ----------------
extern "C" void kernel_launch(void* const* d_in, const int* in_sizes, int n_in,
                              void* d_out, int out_size) {
    const float* fm      = (const float*)d_in[0];
    const float* count   = (const float*)d_in[1];
    const int*   target  = (const int*)d_in[2];
    const float* conv_w  = (const float*)d_in[3];
    const float* conv_b  = (const float*)d_in[4];
    const float* emb     = (const float*)d_in[5];
    const float* gru_wih = (const float*)d_in[6];
    const float* gru_whh = (const float*)d_in[7];
    const float* gru_bih = (const float*)d_in[8];
    const float* gru_bhh = (const float*)d_in[9];
    const float* attn_w  = (const float*)d_in[10];
    const float* attn_b  = (const float*)d_in[11];
    const float* attn_v  = (const float*)d_in[12];
    const float* attn_vb = (const float*)d_in[13];
    const float* cov_w   = (const float*)d_in[14];
    const float* cov_b   = (const float*)d_in[15];
    const float* out_w   = (const float*)d_in[16];
    const float* out_b   = (const float*)d_in[17];
    float* out = (float*)d_out;

    float *pW2, *pPeB, *pE;
    __nv_bfloat16 *pFh, *pFmh, *pW2h;
    cudaGetSymbolAddress((void**)&pFh, g_Fh);
    cudaGetSymbolAddress((void**)&pW2, g_W2);
    cudaGetSymbolAddress((void**)&pPeB, g_peB);
    cudaGetSymbolAddress((void**)&pE, g_E);
    cudaGetSymbolAddress((void**)&pFmh, g_fmh);
    cudaGetSymbolAddress((void**)&pW2h, g_W2h);

    static cudaStream_t s1 = nullptr, s2 = nullptr;
    static cudaEvent_t evPrep = nullptr, evMain = nullptr, evSide = nullptr;
    if (!s1) {
        cudaStreamCreateWithFlags(&s1, cudaStreamNonBlocking);
        cudaStreamCreateWithFlags(&s2, cudaStreamNonBlocking);
        cudaEventCreateWithFlags(&evPrep, cudaEventDisableTiming);
        cudaEventCreateWithFlags(&evMain, cudaEventDisableTiming);
        cudaEventCreateWithFlags(&evSide, cudaEventDisableTiming);
    }
    cudaStream_t s0 = (cudaStream_t)0;

    // s0 (capture origin): prep, then fork
    prep_kernel<<<1024, 256, 0, s0>>>(gru_wih, gru_whh, gru_bih, gru_bhh, conv_w, conv_b);
    cudaEventRecord(evPrep, s0);

    // s1: small GEMMs + W2 convert
    cudaStreamWaitEvent(s1, evPrep, 0);
    sgemm64_kernel<<<dim3(16, 4), 256, 0, s1>>>(attn_w, conv_w, pW2 + 256 * CIN,
                                                256, CIN, H2, nullptr);
    sgemm64_kernel<<<dim3(16, 4), 256, 0, s1>>>(attn_w, pPeB, pE + 256 * LL,
                                                256, LL, H2, attn_b);
    cvt_w2_kernel<<<256, 256, 0, s1>>>();
    cudaEventRecord(evMain, s1);

    // s2: gate-precompute
    cudaStreamWaitEvent(s2, evPrep, 0);
    gemb_kernel<<<CC, 256, 0, s2>>>(emb);
    gcnt_kernel<<<BB, 256, 0, s2>>>(count);
    cudaEventRecord(evSide, s2);

    // s0: fm convert overlaps s1/s2, then join and run main GEMM
    cvt_fm_kernel<<<2048, 256, 0, s0>>>(fm);
    cudaStreamWaitEvent(s0, evMain, 0);
    mma_gemm_kernel<<<dim3(8, 4, BB), 256, 0, s0>>>(pW2h, pFmh, pFh, pE);
    cudaStreamWaitEvent(s0, evSide, 0);

    // loop with PDL chaining
    for (int t = 0; t < TT; t++) {
        pdl(dim3(9, BB), dim3(256), score_kernel, t, 8, count, attn_v, attn_vb,
            cov_w, cov_b, out_w, out_b, out);
        pdl(dim3(8, BB), dim3(256), ctx_kernel, t, target);
        pdl(dim3(128), dim3(256), gru_gemm_kernel);
    }
    pdl(dim3(1, BB), dim3(256), score_kernel, (int)TT, 0, count, attn_v, attn_vb,
        cov_w, cov_b, out_w, out_b, out);
}